// round 11
// baseline (speedup 1.0000x reference)
#include <cuda_runtime.h>
#include <cuda_bf16.h>
#include <math.h>
#include <stdint.h>

#define BATCH 32
#define SEQ 196
#define DMODEL 1024
#define HEADS 8
#define DK 128
#define MROWS (BATCH*SEQ)            // 6272

// ---------------- scratch (static device arrays; no allocations) ----------------
__device__ float g_q[MROWS*DMODEL];
__device__ float g_k[MROWS*DMODEL];
__device__ float g_v[MROWS*DMODEL];
__device__ float g_ctx[MROWS*DMODEL];
__device__ float g_vT[(size_t)BATCH*HEADS*DK*SEQ];      // [bh][n][k] transposed V
__device__ float g_logw[(size_t)BATCH*HEADS*SEQ*SEQ];   // geometry log-weights

__constant__ float c_dim[8] = {
    1.0f, 0.4216965034285822f, 0.1778279410038923f, 0.07498942093324558f,
    0.03162277660168379f, 0.013335214321633241f, 0.005623413251903491f,
    0.0023713737056616554f
};

// ============================================================================
// common MMA helpers
// ============================================================================
__device__ __forceinline__ uint32_t smem_u32(const void* p) {
    uint32_t a;
    asm("{ .reg .u64 t; cvta.to.shared.u64 t, %1; cvt.u32.u64 %0, t; }" : "=r"(a) : "l"(p));
    return a;
}

__device__ __forceinline__ void ldsm4(uint32_t r[4], uint32_t addr) {
    asm volatile("ldmatrix.sync.aligned.m8n8.x4.shared.b16 {%0,%1,%2,%3}, [%4];"
        : "=r"(r[0]), "=r"(r[1]), "=r"(r[2]), "=r"(r[3]) : "r"(addr));
}

__device__ __forceinline__ void mma16816(float d[4], const uint32_t a[4], const uint32_t b[2]) {
    asm volatile("mma.sync.aligned.m16n8k16.row.col.f32.bf16.bf16.f32 "
        "{%0,%1,%2,%3}, {%4,%5,%6,%7}, {%8,%9}, {%0,%1,%2,%3};"
        : "+f"(d[0]), "+f"(d[1]), "+f"(d[2]), "+f"(d[3])
        : "r"(a[0]), "r"(a[1]), "r"(a[2]), "r"(a[3]), "r"(b[0]), "r"(b[1]));
}

__device__ __forceinline__ void split4(float4 v, uint2& hi, uint2& lo) {
    __nv_bfloat162 h0 = __float22bfloat162_rn(make_float2(v.x, v.y));
    __nv_bfloat162 h1 = __float22bfloat162_rn(make_float2(v.z, v.w));
    uint32_t u0 = *(uint32_t*)&h0, u1 = *(uint32_t*)&h1;
    float hx = __uint_as_float(u0 << 16);
    float hy = __uint_as_float(u0 & 0xFFFF0000u);
    float hz = __uint_as_float(u1 << 16);
    float hw = __uint_as_float(u1 & 0xFFFF0000u);
    __nv_bfloat162 l0 = __float22bfloat162_rn(make_float2(v.x - hx, v.y - hy));
    __nv_bfloat162 l1 = __float22bfloat162_rn(make_float2(v.z - hz, v.w - hw));
    hi = make_uint2(u0, u1);
    lo = make_uint2(*(uint32_t*)&l0, *(uint32_t*)&l1);
}

// ============================================================================
// projection GEMM: Y[M,1024] = X[M,1024] @ W[1024,1024]^T + bias
// 256 threads, 8 warps (4m x 2n), warp tile 32x64, KCHUNK=64 (16 barriers).
// ============================================================================
#define KC2 64
#define NCHUNK2 (DMODEL / KC2)       // 16
#define GST2 144                     // 64 bf16 = 128B + 16B pad
#define A2HI 0
#define A2LO (128*GST2)              // 18432
#define B2HI (2*128*GST2)            // 36864
#define B2LO (3*128*GST2)            // 55296
#define BUF2 (4*128*GST2)            // 73728
#define SMEM2 (2*BUF2)               // 147456

// quarter q: rows q*32 + {0,16} + rq ; each thread 2 float4 of A and of B
__device__ __forceinline__ void ldg_q(const float* __restrict__ X,
                                      const float* __restrict__ W,
                                      int m0, int n0, int kc, int rq, int c16,
                                      int q, float4 pa[2], float4 pb[2])
{
    int gk = kc + c16 * 4;
#pragma unroll
    for (int i = 0; i < 2; ++i) {
        int row = q * 32 + i * 16 + rq;
        pa[i] = *(const float4*)(X + (size_t)(m0 + row) * DMODEL + gk);
        pb[i] = *(const float4*)(W + (size_t)(n0 + row) * DMODEL + gk);
    }
}

__device__ __forceinline__ void sts_q(char* bp, const float4 pa[2],
                                      const float4 pb[2], int rq, int c16, int q)
{
#pragma unroll
    for (int i = 0; i < 2; ++i) {
        int row = q * 32 + i * 16 + rq;
        uint32_t off = (uint32_t)row * GST2 + c16 * 8;
        uint2 hi, lo;
        split4(pa[i], hi, lo);
        *(uint2*)(bp + A2HI + off) = hi;
        *(uint2*)(bp + A2LO + off) = lo;
        split4(pb[i], hi, lo);
        *(uint2*)(bp + B2HI + off) = hi;
        *(uint2*)(bp + B2LO + off) = lo;
    }
}

// one k16 step at column kofs, 8-warp layout (warp tile 32x64)
__device__ __forceinline__ void mma_ks2(uint32_t base, int kofs, float acc[2][8][4],
                                        int warp_m, int warp_n, int sub, int i8)
{
    uint32_t aHi[2][4], aLo[2][4];
#pragma unroll
    for (int mt = 0; mt < 2; ++mt) {
        int row = warp_m * 32 + mt * 16 + (sub & 1) * 8 + i8;
        int col = kofs + (sub >> 1) * 8;
        uint32_t ad = base + A2HI + (uint32_t)row * GST2 + col * 2;
        ldsm4(aHi[mt], ad);
        ldsm4(aLo[mt], ad + (A2LO - A2HI));
    }
#pragma unroll
    for (int ntp = 0; ntp < 4; ++ntp) {
        int nr = warp_n * 64 + ntp * 16 + (sub >> 1) * 8 + i8;
        int nc = kofs + (sub & 1) * 8;
        uint32_t bd = base + B2HI + (uint32_t)nr * GST2 + nc * 2;
        uint32_t bHi[4], bLo[4];
        ldsm4(bHi, bd);
        ldsm4(bLo, bd + (B2LO - B2HI));
#pragma unroll
        for (int mt = 0; mt < 2; ++mt) {
#pragma unroll
            for (int nh = 0; nh < 2; ++nh) {
                float* d = acc[mt][ntp * 2 + nh];
                mma16816(d, aHi[mt], &bHi[nh * 2]);
                mma16816(d, aLo[mt], &bHi[nh * 2]);
                mma16816(d, aHi[mt], &bLo[nh * 2]);
            }
        }
    }
}

__device__ __forceinline__ void bf16x3_gemm(const float* __restrict__ X,
                                            const float* __restrict__ W,
                                            const float* __restrict__ bias,
                                            float* __restrict__ Y)
{
    extern __shared__ __align__(16) char sm[];
    const uint32_t smb = smem_u32(sm);
    const int tid = threadIdx.x;
    const int lane = tid & 31, w = tid >> 5;
    const int warp_m = w & 3, warp_n = w >> 2;
    const int m0 = blockIdx.y * 128, n0 = blockIdx.x * 128;
    const int rq = tid >> 4, c16 = tid & 15;     // loader coords: 16 rows x 16 float4-cols
    const int sub = lane >> 3, i8 = lane & 7;

    float acc[2][8][4];
#pragma unroll
    for (int mt = 0; mt < 2; mt++)
#pragma unroll
        for (int nt = 0; nt < 8; nt++)
#pragma unroll
            for (int e = 0; e < 4; e++) acc[mt][nt][e] = 0.f;

    float4 pa[2], pb[2];

    // prolog: stage chunk 0 (4 quarters)
#pragma unroll
    for (int q = 0; q < 4; ++q) {
        ldg_q(X, W, m0, n0, 0, rq, c16, q, pa, pb);
        sts_q(sm, pa, pb, rq, c16, q);
    }
    __syncthreads();

    for (int c = 0; c < NCHUNK2; ++c) {
        const uint32_t base = smb + (uint32_t)(c & 1) * BUF2;
        char* nxt = sm + ((c + 1) & 1) * BUF2;
        const bool pre = (c + 1 < NCHUNK2);
        const int kc1 = (c + 1) * KC2;

        if (pre) ldg_q(X, W, m0, n0, kc1, rq, c16, 0, pa, pb);
        mma_ks2(base, 0, acc, warp_m, warp_n, sub, i8);
        if (pre) {
            sts_q(nxt, pa, pb, rq, c16, 0);
            ldg_q(X, W, m0, n0, kc1, rq, c16, 1, pa, pb);
        }
        mma_ks2(base, 16, acc, warp_m, warp_n, sub, i8);
        if (pre) {
            sts_q(nxt, pa, pb, rq, c16, 1);
            ldg_q(X, W, m0, n0, kc1, rq, c16, 2, pa, pb);
        }
        mma_ks2(base, 32, acc, warp_m, warp_n, sub, i8);
        if (pre) {
            sts_q(nxt, pa, pb, rq, c16, 2);
            ldg_q(X, W, m0, n0, kc1, rq, c16, 3, pa, pb);
        }
        mma_ks2(base, 48, acc, warp_m, warp_n, sub, i8);
        if (pre) sts_q(nxt, pa, pb, rq, c16, 3);
        __syncthreads();
    }

    const int g = lane >> 2, t4 = lane & 3;
#pragma unroll
    for (int mt = 0; mt < 2; ++mt) {
        int row = m0 + warp_m * 32 + mt * 16 + g;
#pragma unroll
        for (int nt = 0; nt < 8; ++nt) {
            int col = n0 + warp_n * 64 + nt * 8 + 2 * t4;
            float b0 = bias[col], b1 = bias[col + 1];
            float* d = acc[mt][nt];
            *(float2*)&Y[(size_t)row * DMODEL + col] = make_float2(d[0] + b0, d[1] + b1);
            *(float2*)&Y[(size_t)(row + 8) * DMODEL + col] = make_float2(d[2] + b0, d[3] + b1);
        }
    }
}

__global__ void __launch_bounds__(256, 1)
qkv_mma(const float* __restrict__ xq, const float* __restrict__ xk,
        const float* __restrict__ xv,
        const float* __restrict__ wq, const float* __restrict__ wk,
        const float* __restrict__ wv,
        const float* __restrict__ bq, const float* __restrict__ bk,
        const float* __restrict__ bv)
{
    int z = blockIdx.z;
    const float* X = (z == 0) ? xq : (z == 1) ? xk : xv;
    const float* W = (z == 0) ? wq : (z == 1) ? wk : wv;
    const float* bias = (z == 0) ? bq : (z == 1) ? bk : bv;
    float* Y = (z == 0) ? g_q : (z == 1) ? g_k : g_v;
    bf16x3_gemm(X, W, bias, Y);
}

__global__ void __launch_bounds__(256, 1)
out_mma(const float* __restrict__ Wo, const float* __restrict__ bo,
        float* __restrict__ Y)
{
    bf16x3_gemm(g_ctx, Wo, bo, Y);
}

// ============================================================================
// fused attention — R9 proven config (512 threads, 32x32 warp tiles,
// dead-tile skip). UNCHANGED.
// ============================================================================
#define KCHUNK 32
#define GSTRIDE 80
#define OFF_AHI 0
#define OFF_ALO (128*GSTRIDE)
#define OFF_BHI (2*128*GSTRIDE)
#define OFF_BLO (3*128*GSTRIDE)
#define BUFSZ   (4*128*GSTRIDE)      // 40960
#define SSTRIDE 224
#define SMEM_FUSED (2*BUFSZ + 128*SSTRIDE*4)   // 196608

__device__ __forceinline__ void stage_store512(char* bp, const float4 pa[2],
                                               const float4 pb[2], int r_ld, int c4)
{
#pragma unroll
    for (int it = 0; it < 2; ++it) {
        uint32_t off = (uint32_t)(it * 64 + r_ld) * GSTRIDE + c4 * 8;
        uint2 hi, lo;
        split4(pa[it], hi, lo);
        *(uint2*)(bp + OFF_AHI + off) = hi;
        *(uint2*)(bp + OFF_ALO + off) = lo;
        split4(pb[it], hi, lo);
        *(uint2*)(bp + OFF_BHI + off) = hi;
        *(uint2*)(bp + OFF_BLO + off) = lo;
    }
}

__device__ __forceinline__ void mma_chunk512(uint32_t base, float acc[2][4][4],
                                             int warp_m, int warp_n, int sub, int i8)
{
#pragma unroll
    for (int ks = 0; ks < 2; ++ks) {
        const int kofs = ks * 16;
        uint32_t aHi[2][4], aLo[2][4];
#pragma unroll
        for (int mt = 0; mt < 2; ++mt) {
            int row = warp_m * 32 + mt * 16 + (sub & 1) * 8 + i8;
            int col = kofs + (sub >> 1) * 8;
            uint32_t ad = base + OFF_AHI + (uint32_t)row * GSTRIDE + col * 2;
            ldsm4(aHi[mt], ad);
            ldsm4(aLo[mt], ad + (OFF_ALO - OFF_AHI));
        }
#pragma unroll
        for (int ntp = 0; ntp < 2; ++ntp) {
            int nr = warp_n * 32 + ntp * 16 + (sub >> 1) * 8 + i8;
            int nc = kofs + (sub & 1) * 8;
            uint32_t bd = base + OFF_BHI + (uint32_t)nr * GSTRIDE + nc * 2;
            uint32_t bHi[4], bLo[4];
            ldsm4(bHi, bd);
            ldsm4(bLo, bd + (OFF_BLO - OFF_BHI));
#pragma unroll
            for (int mt = 0; mt < 2; ++mt) {
#pragma unroll
                for (int nh = 0; nh < 2; ++nh) {
                    float* d = acc[mt][ntp * 2 + nh];
                    mma16816(d, aHi[mt], &bHi[nh * 2]);
                    mma16816(d, aLo[mt], &bHi[nh * 2]);
                    mma16816(d, aHi[mt], &bLo[nh * 2]);
                }
            }
        }
    }
}

__global__ void __launch_bounds__(512, 1)
fused_attn()
{
    extern __shared__ __align__(16) char sm[];
    const uint32_t smb = smem_u32(sm);
    float* sS = (float*)(sm + 2 * BUFSZ);        // 128 x SSTRIDE fp32

    const int bh = blockIdx.y;
    const int b = bh >> 3, h = bh & 7;
    const int m0 = blockIdx.x * 128;
    const float* Q  = g_q + (size_t)b * SEQ * DMODEL + h * DK;
    const float* Kp = g_k + (size_t)b * SEQ * DMODEL + h * DK;
    const float* LW = g_logw + (size_t)bh * SEQ * SEQ;
    const float* Vt = g_vT + (size_t)bh * DK * SEQ;

    const int tid = threadIdx.x;
    const int lane = tid & 31, w = tid >> 5;     // w: 0..15
    const int warp_m = w & 3, warp_n = w >> 2;   // 4 x 4 warp grid
    const int r_ld = tid >> 3, c4 = tid & 7;     // r_ld: 0..63
    const int sub = lane >> 3, i8 = lane & 7;
    const int g = lane >> 2, t4 = lane & 3;
    const float4 z4 = make_float4(0.f, 0.f, 0.f, 0.f);

    const bool m_live = (m0 + warp_m * 32) < SEQ;

    float acc[2][4][4];
    float4 pa[2], pb[2];

    // ======== Phase A: S = Q K^T * scale + logw (two 128x128 n-halves) ========
    const float scale = 0.08838834764831845f;   // 1/sqrt(128)
#pragma unroll 1
    for (int nt2 = 0; nt2 < 2; ++nt2) {
        const int n0 = nt2 * 128;
        const bool live = m_live && ((n0 + warp_n * 32) < SEQ);
#pragma unroll
        for (int mt = 0; mt < 2; mt++)
#pragma unroll
            for (int nt = 0; nt < 4; nt++)
#pragma unroll
                for (int e = 0; e < 4; e++) acc[mt][nt][e] = 0.f;

        {
            int gk = c4 * 4;
#pragma unroll
            for (int it = 0; it < 2; ++it) {
                int am = m0 + it * 64 + r_ld;
                int bn = n0 + it * 64 + r_ld;
                pa[it] = (am < SEQ) ? *(const float4*)(Q + (size_t)am * DMODEL + gk) : z4;
                pb[it] = (bn < SEQ) ? *(const float4*)(Kp + (size_t)bn * DMODEL + gk) : z4;
            }
            stage_store512(sm, pa, pb, r_ld, c4);
        }
        __syncthreads();

        for (int c = 0; c < 4; ++c) {          // DK=128 -> 4 chunks
            if (c + 1 < 4) {
                int gk = (c + 1) * KCHUNK + c4 * 4;
#pragma unroll
                for (int it = 0; it < 2; ++it) {
                    int am = m0 + it * 64 + r_ld;
                    int bn = n0 + it * 64 + r_ld;
                    pa[it] = (am < SEQ) ? *(const float4*)(Q + (size_t)am * DMODEL + gk) : z4;
                    pb[it] = (bn < SEQ) ? *(const float4*)(Kp + (size_t)bn * DMODEL + gk) : z4;
                }
            }
            if (live)
                mma_chunk512(smb + (uint32_t)(c & 1) * BUFSZ, acc, warp_m, warp_n, sub, i8);
            if (c + 1 < 4)
                stage_store512(sm + ((c + 1) & 1) * BUFSZ, pa, pb, r_ld, c4);
            __syncthreads();
        }

        // epilogue -> sS (+logw)
#pragma unroll
        for (int mt = 0; mt < 2; ++mt) {
            int rl = warp_m * 32 + mt * 16 + g;        // local row 0..127
            int m = m0 + rl;
#pragma unroll
            for (int nt = 0; nt < 4; ++nt) {
                int col = n0 + warp_n * 32 + nt * 8 + 2 * t4;
                float* d = acc[mt][nt];
                if (col < SEQ) {
                    bool mok = (m < SEQ);
                    float l0 = mok ? LW[(size_t)m * SEQ + col] : 0.f;
                    float l1 = mok ? LW[(size_t)m * SEQ + col + 1] : 0.f;
                    *(float2*)&sS[(size_t)rl * SSTRIDE + col] =
                        make_float2(fmaf(d[0], scale, l0), fmaf(d[1], scale, l1));
                    bool m8 = (m + 8 < SEQ);
                    float l2 = m8 ? LW[(size_t)(m + 8) * SEQ + col] : 0.f;
                    float l3 = m8 ? LW[(size_t)(m + 8) * SEQ + col + 1] : 0.f;
                    *(float2*)&sS[(size_t)(rl + 8) * SSTRIDE + col] =
                        make_float2(fmaf(d[2], scale, l2), fmaf(d[3], scale, l3));
                }
            }
        }
        __syncthreads();
    }

    // ======== Phase B: softmax rows in SMEM (16 warps x 8 rows) ========
    {
#pragma unroll 1
        for (int j = 0; j < 8; ++j) {
            int r = w * 8 + j;
            float* row = sS + (size_t)r * SSTRIDE;
            float x[7];
            float mx = -1e30f;
#pragma unroll
            for (int i = 0; i < 7; ++i) {
                int cidx = lane + i * 32;
                x[i] = (cidx < SEQ) ? row[cidx] : -1e30f;
                mx = fmaxf(mx, x[i]);
            }
#pragma unroll
            for (int o = 16; o > 0; o >>= 1) mx = fmaxf(mx, __shfl_xor_sync(0xffffffffu, mx, o));
            float sum = 0.f;
#pragma unroll
            for (int i = 0; i < 7; ++i) {
                x[i] = expf(x[i] - mx);
                sum += x[i];
            }
#pragma unroll
            for (int o = 16; o > 0; o >>= 1) sum += __shfl_xor_sync(0xffffffffu, sum, o);
            float inv = 1.0f / sum;
#pragma unroll
            for (int i = 0; i < 7; ++i) {
                int cidx = lane + i * 32;
                if (cidx < SEQ) row[cidx] = x[i] * inv;
            }
            if (lane < 28) row[SEQ + lane] = 0.f;     // zero pad cols 196..223
        }
    }
    __syncthreads();

    // ======== Phase C: ctx = P @ V^T (output 128x128, n = DK dense) ========
#pragma unroll
    for (int mt = 0; mt < 2; mt++)
#pragma unroll
        for (int nt = 0; nt < 4; nt++)
#pragma unroll
            for (int e = 0; e < 4; e++) acc[mt][nt][e] = 0.f;

    const int nchunkC = 7;                        // ceil(196/32)
    {
        int gk = c4 * 4;
#pragma unroll
        for (int it = 0; it < 2; ++it) {
            int rr = it * 64 + r_ld;
            pa[it] = *(const float4*)(sS + (size_t)rr * SSTRIDE + gk);
            pb[it] = *(const float4*)(Vt + (size_t)rr * SEQ + gk);
        }
        stage_store512(sm, pa, pb, r_ld, c4);
    }
    __syncthreads();

    for (int c = 0; c < nchunkC; ++c) {
        if (c + 1 < nchunkC) {
            int gk = (c + 1) * KCHUNK + c4 * 4;
            bool kok = gk < SEQ;
#pragma unroll
            for (int it = 0; it < 2; ++it) {
                int rr = it * 64 + r_ld;
                pa[it] = *(const float4*)(sS + (size_t)rr * SSTRIDE + gk);   // pad zeroed
                pb[it] = kok ? *(const float4*)(Vt + (size_t)rr * SEQ + gk) : z4;
            }
        }
        if (m_live)
            mma_chunk512(smb + (uint32_t)(c & 1) * BUFSZ, acc, warp_m, warp_n, sub, i8);
        if (c + 1 < nchunkC)
            stage_store512(sm + ((c + 1) & 1) * BUFSZ, pa, pb, r_ld, c4);
        __syncthreads();
    }

    // epilogue -> g_ctx
    float* C = g_ctx + (size_t)b * SEQ * DMODEL + h * DK;
#pragma unroll
    for (int mt = 0; mt < 2; ++mt) {
        int m = m0 + warp_m * 32 + mt * 16 + g;
#pragma unroll
        for (int nt = 0; nt < 4; ++nt) {
            int col = warp_n * 32 + nt * 8 + 2 * t4;
            float* d = acc[mt][nt];
            if (m < SEQ)
                *(float2*)(C + (size_t)m * DMODEL + col) = make_float2(d[0], d[1]);
            if (m + 8 < SEQ)
                *(float2*)(C + (size_t)(m + 8) * DMODEL + col) = make_float2(d[2], d[3]);
        }
    }
}

// ---------------- V transpose: g_vT[bh][n][k] = g_v[b][k][h*DK+n] ----------------
__global__ void vT_kernel()
{
    __shared__ float t[32][33];
    int bh = blockIdx.z;
    int b = bh >> 3, h = bh & 7;
    int k0 = blockIdx.x * 32, n0 = blockIdx.y * 32;
    int tx = threadIdx.x, ty = threadIdx.y;   // 32 x 8
#pragma unroll
    for (int j = 0; j < 4; ++j) {
        int k = k0 + ty + j * 8;
        t[ty + j * 8][tx] = (k < SEQ)
            ? g_v[((size_t)b * SEQ + k) * DMODEL + h * DK + n0 + tx] : 0.f;
    }
    __syncthreads();
#pragma unroll
    for (int j = 0; j < 4; ++j) {
        int n = n0 + ty + j * 8;
        int k = k0 + tx;
        if (k < SEQ)
            g_vT[(size_t)bh * DK * SEQ + (size_t)n * SEQ + k] = t[tx][ty + j * 8];
    }
}

// ---------------- geometry embedding -> logw[b,h,n,m] ----------------
__global__ void logw_kernel(const float* __restrict__ boxes,
                            const float* __restrict__ WGw,
                            const float* __restrict__ WGb)
{
    __shared__ float sW[8][64];
    __shared__ float sB[8];
    __shared__ float sbn[4];
    int t = threadIdx.x;
    int b = blockIdx.x / SEQ;
    int n = blockIdx.x % SEQ;

    for (int i = t; i < 512; i += blockDim.x) sW[i >> 6][i & 63] = WGw[i];
    if (t < 8) sB[t] = WGb[t];
    if (t == 0) {
        const float* bp = boxes + ((size_t)b * SEQ + n) * 4;
        float xmn = bp[0], ymn = bp[1], xmx = bp[2], ymx = bp[3];
        sbn[0] = (xmn + xmx) * 0.5f;
        sbn[1] = (ymn + ymx) * 0.5f;
        sbn[2] = (xmx - xmn) + 1.0f;
        sbn[3] = (ymx - ymn) + 1.0f;
    }
    __syncthreads();

    int m = t;
    if (m >= SEQ) return;

    const float* bm = boxes + ((size_t)b * SEQ + m) * 4;
    float xmn = bm[0], ymn = bm[1], xmx = bm[2], ymx = bm[3];
    float cxm = (xmn + xmx) * 0.5f, cym = (ymn + ymx) * 0.5f;
    float wm = (xmx - xmn) + 1.0f, hm = (ymx - ymn) + 1.0f;
    float cxn = sbn[0], cyn = sbn[1], wn = sbn[2], hn = sbn[3];

    float pos[4];
    pos[0] = logf(fmaxf(fabsf((cxn - cxm) / wn), 1e-3f));
    pos[1] = logf(fmaxf(fabsf((cyn - cym) / hn), 1e-3f));
    pos[2] = logf(wn / wm);
    pos[3] = logf(hn / hm);

    float acc[8];
#pragma unroll
    for (int h = 0; h < 8; h++) acc[h] = sB[h];

#pragma unroll
    for (int c = 0; c < 4; c++) {
        float p = 100.0f * pos[c];
#pragma unroll
        for (int j = 0; j < 8; j++) {
            float s, co;
            __sincosf(p * c_dim[j], &s, &co);
            int f = c * 8 + j;
#pragma unroll
            for (int h = 0; h < 8; h++)
                acc[h] += s * sW[h][f] + co * sW[h][f + 32];
        }
    }

    size_t base = ((size_t)b * HEADS) * SEQ * SEQ + (size_t)n * SEQ + m;
#pragma unroll
    for (int h = 0; h < 8; h++) {
        float wg = fmaxf(acc[h], 1e-6f);
        g_logw[base + (size_t)h * SEQ * SEQ] = logf(wg);
    }
}

// ---------------- launch ----------------
extern "C" void kernel_launch(void* const* d_in, const int* in_sizes, int n_in,
                              void* d_out, int out_size)
{
    const float* xq  = (const float*)d_in[0];
    const float* xk  = (const float*)d_in[1];
    const float* xv  = (const float*)d_in[2];
    const float* box = (const float*)d_in[3];
    const float* Wq  = (const float*)d_in[4];
    const float* bq  = (const float*)d_in[5];
    const float* Wk  = (const float*)d_in[6];
    const float* bk  = (const float*)d_in[7];
    const float* Wv  = (const float*)d_in[8];
    const float* bv  = (const float*)d_in[9];
    const float* Wo  = (const float*)d_in[10];
    const float* bo  = (const float*)d_in[11];
    const float* WGw = (const float*)d_in[12];
    const float* WGb = (const float*)d_in[13];
    float* out = (float*)d_out;

    cudaFuncSetAttribute(qkv_mma,    cudaFuncAttributeMaxDynamicSharedMemorySize, SMEM2);
    cudaFuncSetAttribute(out_mma,    cudaFuncAttributeMaxDynamicSharedMemorySize, SMEM2);
    cudaFuncSetAttribute(fused_attn, cudaFuncAttributeMaxDynamicSharedMemorySize, SMEM_FUSED);

    // 1) Q/K/V projections (bf16x3 MMA, KCHUNK=64)
    qkv_mma<<<dim3(DMODEL / 128, MROWS / 128, 3), 256, SMEM2>>>(
        xq, xk, xv, Wq, Wk, Wv, bq, bk, bv);

    // 2) transpose V per head
    vT_kernel<<<dim3(7, 4, BATCH * HEADS), dim3(32, 8)>>>();

    // 3) geometry relation log-weights
    logw_kernel<<<BATCH * SEQ, 224>>>(box, WGw, WGb);

    // 4) fused: S = QK^T/sqrt(dk)+logw -> softmax -> P@V  (512 threads, dead-tile skip)
    fused_attn<<<dim3(2, BATCH * HEADS), 512, SMEM_FUSED>>>();

    // 5) output projection into d_out (KCHUNK=64)
    out_mma<<<dim3(DMODEL / 128, MROWS / 128, 1), 256, SMEM2>>>(Wo, bo, out);
}

// round 12
// speedup vs baseline: 1.3221x; 1.3221x over previous
#include <cuda_runtime.h>
#include <cuda_bf16.h>
#include <cuda_fp16.h>
#include <math.h>
#include <stdint.h>

#define BATCH 32
#define SEQ 196
#define DMODEL 1024
#define HEADS 8
#define DK 128
#define MROWS (BATCH*SEQ)            // 6272

// ---------------- scratch (static device arrays; no allocations) ----------------
__device__ float g_q[MROWS*DMODEL];
__device__ float g_k[MROWS*DMODEL];
__device__ float g_v[MROWS*DMODEL];
__device__ float g_ctx[MROWS*DMODEL];
__device__ float g_vT[(size_t)BATCH*HEADS*DK*SEQ];      // [bh][n][k] transposed V
__device__ float g_logw[(size_t)BATCH*HEADS*SEQ*SEQ];   // geometry log-weights

__constant__ float c_dim[8] = {
    1.0f, 0.4216965034285822f, 0.1778279410038923f, 0.07498942093324558f,
    0.03162277660168379f, 0.013335214321633241f, 0.005623413251903491f,
    0.0023713737056616554f
};

// ============================================================================
// common helpers
// ============================================================================
__device__ __forceinline__ uint32_t smem_u32(const void* p) {
    uint32_t a;
    asm("{ .reg .u64 t; cvta.to.shared.u64 t, %1; cvt.u32.u64 %0, t; }" : "=r"(a) : "l"(p));
    return a;
}

__device__ __forceinline__ void ldsm4(uint32_t r[4], uint32_t addr) {
    asm volatile("ldmatrix.sync.aligned.m8n8.x4.shared.b16 {%0,%1,%2,%3}, [%4];"
        : "=r"(r[0]), "=r"(r[1]), "=r"(r[2]), "=r"(r[3]) : "r"(addr));
}

// bf16 MMA (fused_attn path)
__device__ __forceinline__ void mma16816(float d[4], const uint32_t a[4], const uint32_t b[2]) {
    asm volatile("mma.sync.aligned.m16n8k16.row.col.f32.bf16.bf16.f32 "
        "{%0,%1,%2,%3}, {%4,%5,%6,%7}, {%8,%9}, {%0,%1,%2,%3};"
        : "+f"(d[0]), "+f"(d[1]), "+f"(d[2]), "+f"(d[3])
        : "r"(a[0]), "r"(a[1]), "r"(a[2]), "r"(a[3]), "r"(b[0]), "r"(b[1]));
}

// fp16 MMA (projection path)
__device__ __forceinline__ void mma16816h(float d[4], const uint32_t a[4], const uint32_t b[2]) {
    asm volatile("mma.sync.aligned.m16n8k16.row.col.f32.f16.f16.f32 "
        "{%0,%1,%2,%3}, {%4,%5,%6,%7}, {%8,%9}, {%0,%1,%2,%3};"
        : "+f"(d[0]), "+f"(d[1]), "+f"(d[2]), "+f"(d[3])
        : "r"(a[0]), "r"(a[1]), "r"(a[2]), "r"(a[3]), "r"(b[0]), "r"(b[1]));
}

// bf16 hi/lo split (fused_attn path)
__device__ __forceinline__ void split4(float4 v, uint2& hi, uint2& lo) {
    __nv_bfloat162 h0 = __float22bfloat162_rn(make_float2(v.x, v.y));
    __nv_bfloat162 h1 = __float22bfloat162_rn(make_float2(v.z, v.w));
    uint32_t u0 = *(uint32_t*)&h0, u1 = *(uint32_t*)&h1;
    float hx = __uint_as_float(u0 << 16);
    float hy = __uint_as_float(u0 & 0xFFFF0000u);
    float hz = __uint_as_float(u1 << 16);
    float hw = __uint_as_float(u1 & 0xFFFF0000u);
    __nv_bfloat162 l0 = __float22bfloat162_rn(make_float2(v.x - hx, v.y - hy));
    __nv_bfloat162 l1 = __float22bfloat162_rn(make_float2(v.z - hz, v.w - hw));
    hi = make_uint2(u0, u1);
    lo = make_uint2(*(uint32_t*)&l0, *(uint32_t*)&l1);
}

// fp16 hi/lo split (projection A side; exact to ~2^-22)
__device__ __forceinline__ void split4h(float4 v, uint2& hi, uint2& lo) {
    __half2 h0 = __floats2half2_rn(v.x, v.y);
    __half2 h1 = __floats2half2_rn(v.z, v.w);
    __half2 l0 = __floats2half2_rn(v.x - __low2float(h0), v.y - __high2float(h0));
    __half2 l1 = __floats2half2_rn(v.z - __low2float(h1), v.w - __high2float(h1));
    hi = make_uint2(*(uint32_t*)&h0, *(uint32_t*)&h1);
    lo = make_uint2(*(uint32_t*)&l0, *(uint32_t*)&l1);
}

// fp16 plain convert (projection W side)
__device__ __forceinline__ uint2 cvt4h(float4 v) {
    __half2 h0 = __floats2half2_rn(v.x, v.y);
    __half2 h1 = __floats2half2_rn(v.z, v.w);
    return make_uint2(*(uint32_t*)&h0, *(uint32_t*)&h1);
}

// ============================================================================
// projection GEMM (fp16x2): Y[M,1024] = X[M,1024] @ W[1024,1024]^T + bias
// 256 threads, 8 warps (4m x 2n), warp tile 32x64, KCHUNK=32 (R9 skeleton).
// A split hi/lo fp16 (2 MMAs), W single fp16.
// ============================================================================
#define PKC 32
#define PNCH (DMODEL / PKC)          // 32
#define PGS 80                       // 32 fp16 = 64B + 16B pad
#define PA_HI 0
#define PA_LO (128*PGS)              // 10240
#define PB_HI (2*128*PGS)            // 20480
#define PBUF  (3*128*PGS)            // 30720
#define PSMEM (2*PBUF)               // 61440

__device__ __forceinline__ void stage_store_p(char* bp, const float4 pa[4],
                                              const float4 pb[4], int r_ld, int c4)
{
#pragma unroll
    for (int it = 0; it < 4; ++it) {
        uint32_t off = (uint32_t)(it * 32 + r_ld) * PGS + c4 * 8;
        uint2 hi, lo;
        split4h(pa[it], hi, lo);
        *(uint2*)(bp + PA_HI + off) = hi;
        *(uint2*)(bp + PA_LO + off) = lo;
        *(uint2*)(bp + PB_HI + off) = cvt4h(pb[it]);
    }
}

// one 32-K chunk: 2 k16 steps, per step 32 fp16 MMAs + 8 LDSM
__device__ __forceinline__ void mma_chunk_p(uint32_t base, float acc[2][8][4],
                                            int warp_m, int warp_n, int sub, int i8)
{
#pragma unroll
    for (int ks = 0; ks < 2; ++ks) {
        const int kofs = ks * 16;
        uint32_t aHi[2][4], aLo[2][4];
#pragma unroll
        for (int mt = 0; mt < 2; ++mt) {
            int row = warp_m * 32 + mt * 16 + (sub & 1) * 8 + i8;
            int col = kofs + (sub >> 1) * 8;
            uint32_t ad = base + PA_HI + (uint32_t)row * PGS + col * 2;
            ldsm4(aHi[mt], ad);
            ldsm4(aLo[mt], ad + (PA_LO - PA_HI));
        }
#pragma unroll
        for (int ntp = 0; ntp < 4; ++ntp) {
            int nr = warp_n * 64 + ntp * 16 + (sub >> 1) * 8 + i8;
            int nc = kofs + (sub & 1) * 8;
            uint32_t bd = base + PB_HI + (uint32_t)nr * PGS + nc * 2;
            uint32_t bH[4];
            ldsm4(bH, bd);
#pragma unroll
            for (int mt = 0; mt < 2; ++mt) {
#pragma unroll
                for (int nh = 0; nh < 2; ++nh) {
                    float* d = acc[mt][ntp * 2 + nh];
                    mma16816h(d, aHi[mt], &bH[nh * 2]);
                    mma16816h(d, aLo[mt], &bH[nh * 2]);
                }
            }
        }
    }
}

__device__ __forceinline__ void fp16x2_gemm(const float* __restrict__ X,
                                            const float* __restrict__ W,
                                            const float* __restrict__ bias,
                                            float* __restrict__ Y)
{
    extern __shared__ __align__(16) char sm[];
    const uint32_t smb = smem_u32(sm);
    const int tid = threadIdx.x;
    const int lane = tid & 31, w = tid >> 5;
    const int warp_m = w & 3, warp_n = w >> 2;
    const int m0 = blockIdx.y * 128, n0 = blockIdx.x * 128;
    const int r_ld = tid >> 3, c4 = tid & 7;
    const int sub = lane >> 3, i8 = lane & 7;

    float acc[2][8][4];
#pragma unroll
    for (int mt = 0; mt < 2; mt++)
#pragma unroll
        for (int nt = 0; nt < 8; nt++)
#pragma unroll
            for (int e = 0; e < 4; e++) acc[mt][nt][e] = 0.f;

    float4 pa[4], pb[4];

    {
        const float* Ag = X + c4 * 4;
        const float* Bg = W + c4 * 4;
#pragma unroll
        for (int it = 0; it < 4; ++it) {
            pa[it] = *(const float4*)(Ag + (size_t)(m0 + it * 32 + r_ld) * DMODEL);
            pb[it] = *(const float4*)(Bg + (size_t)(n0 + it * 32 + r_ld) * DMODEL);
        }
        stage_store_p(sm, pa, pb, r_ld, c4);
    }
    __syncthreads();

    for (int c = 0; c < PNCH; ++c) {
        if (c + 1 < PNCH) {
            const int kc = (c + 1) * PKC;
            const float* Ag = X + kc + c4 * 4;
            const float* Bg = W + kc + c4 * 4;
#pragma unroll
            for (int it = 0; it < 4; ++it) {
                pa[it] = *(const float4*)(Ag + (size_t)(m0 + it * 32 + r_ld) * DMODEL);
                pb[it] = *(const float4*)(Bg + (size_t)(n0 + it * 32 + r_ld) * DMODEL);
            }
        }
        mma_chunk_p(smb + (uint32_t)(c & 1) * PBUF, acc, warp_m, warp_n, sub, i8);
        if (c + 1 < PNCH)
            stage_store_p(sm + ((c + 1) & 1) * PBUF, pa, pb, r_ld, c4);
        __syncthreads();
    }

    const int g = lane >> 2, t4 = lane & 3;
#pragma unroll
    for (int mt = 0; mt < 2; ++mt) {
        int row = m0 + warp_m * 32 + mt * 16 + g;
#pragma unroll
        for (int nt = 0; nt < 8; ++nt) {
            int col = n0 + warp_n * 64 + nt * 8 + 2 * t4;
            float b0 = bias[col], b1 = bias[col + 1];
            float* d = acc[mt][nt];
            *(float2*)&Y[(size_t)row * DMODEL + col] = make_float2(d[0] + b0, d[1] + b1);
            *(float2*)&Y[(size_t)(row + 8) * DMODEL + col] = make_float2(d[2] + b0, d[3] + b1);
        }
    }
}

__global__ void __launch_bounds__(256, 1)
qkv_mma(const float* __restrict__ xq, const float* __restrict__ xk,
        const float* __restrict__ xv,
        const float* __restrict__ wq, const float* __restrict__ wk,
        const float* __restrict__ wv,
        const float* __restrict__ bq, const float* __restrict__ bk,
        const float* __restrict__ bv)
{
    int z = blockIdx.z;
    const float* X = (z == 0) ? xq : (z == 1) ? xk : xv;
    const float* W = (z == 0) ? wq : (z == 1) ? wk : wv;
    const float* bias = (z == 0) ? bq : (z == 1) ? bk : bv;
    float* Y = (z == 0) ? g_q : (z == 1) ? g_k : g_v;
    fp16x2_gemm(X, W, bias, Y);
}

__global__ void __launch_bounds__(256, 1)
out_mma(const float* __restrict__ Wo, const float* __restrict__ bo,
        float* __restrict__ Y)
{
    fp16x2_gemm(g_ctx, Wo, bo, Y);
}

// ============================================================================
// fused attention — R9 proven config (512 threads, bf16x3, 32x32 warp tiles,
// dead-tile skip). UNCHANGED.
// ============================================================================
#define KCHUNK 32
#define GSTRIDE 80
#define OFF_AHI 0
#define OFF_ALO (128*GSTRIDE)
#define OFF_BHI (2*128*GSTRIDE)
#define OFF_BLO (3*128*GSTRIDE)
#define BUFSZ   (4*128*GSTRIDE)      // 40960
#define SSTRIDE 224
#define SMEM_FUSED (2*BUFSZ + 128*SSTRIDE*4)   // 196608

__device__ __forceinline__ void stage_store512(char* bp, const float4 pa[2],
                                               const float4 pb[2], int r_ld, int c4)
{
#pragma unroll
    for (int it = 0; it < 2; ++it) {
        uint32_t off = (uint32_t)(it * 64 + r_ld) * GSTRIDE + c4 * 8;
        uint2 hi, lo;
        split4(pa[it], hi, lo);
        *(uint2*)(bp + OFF_AHI + off) = hi;
        *(uint2*)(bp + OFF_ALO + off) = lo;
        split4(pb[it], hi, lo);
        *(uint2*)(bp + OFF_BHI + off) = hi;
        *(uint2*)(bp + OFF_BLO + off) = lo;
    }
}

__device__ __forceinline__ void mma_chunk512(uint32_t base, float acc[2][4][4],
                                             int warp_m, int warp_n, int sub, int i8)
{
#pragma unroll
    for (int ks = 0; ks < 2; ++ks) {
        const int kofs = ks * 16;
        uint32_t aHi[2][4], aLo[2][4];
#pragma unroll
        for (int mt = 0; mt < 2; ++mt) {
            int row = warp_m * 32 + mt * 16 + (sub & 1) * 8 + i8;
            int col = kofs + (sub >> 1) * 8;
            uint32_t ad = base + OFF_AHI + (uint32_t)row * GSTRIDE + col * 2;
            ldsm4(aHi[mt], ad);
            ldsm4(aLo[mt], ad + (OFF_ALO - OFF_AHI));
        }
#pragma unroll
        for (int ntp = 0; ntp < 2; ++ntp) {
            int nr = warp_n * 32 + ntp * 16 + (sub >> 1) * 8 + i8;
            int nc = kofs + (sub & 1) * 8;
            uint32_t bd = base + OFF_BHI + (uint32_t)nr * GSTRIDE + nc * 2;
            uint32_t bHi[4], bLo[4];
            ldsm4(bHi, bd);
            ldsm4(bLo, bd + (OFF_BLO - OFF_BHI));
#pragma unroll
            for (int mt = 0; mt < 2; ++mt) {
#pragma unroll
                for (int nh = 0; nh < 2; ++nh) {
                    float* d = acc[mt][ntp * 2 + nh];
                    mma16816(d, aHi[mt], &bHi[nh * 2]);
                    mma16816(d, aLo[mt], &bHi[nh * 2]);
                    mma16816(d, aHi[mt], &bLo[nh * 2]);
                }
            }
        }
    }
}

__global__ void __launch_bounds__(512, 1)
fused_attn()
{
    extern __shared__ __align__(16) char sm[];
    const uint32_t smb = smem_u32(sm);
    float* sS = (float*)(sm + 2 * BUFSZ);        // 128 x SSTRIDE fp32

    const int bh = blockIdx.y;
    const int b = bh >> 3, h = bh & 7;
    const int m0 = blockIdx.x * 128;
    const float* Q  = g_q + (size_t)b * SEQ * DMODEL + h * DK;
    const float* Kp = g_k + (size_t)b * SEQ * DMODEL + h * DK;
    const float* LW = g_logw + (size_t)bh * SEQ * SEQ;
    const float* Vt = g_vT + (size_t)bh * DK * SEQ;

    const int tid = threadIdx.x;
    const int lane = tid & 31, w = tid >> 5;     // w: 0..15
    const int warp_m = w & 3, warp_n = w >> 2;   // 4 x 4 warp grid
    const int r_ld = tid >> 3, c4 = tid & 7;     // r_ld: 0..63
    const int sub = lane >> 3, i8 = lane & 7;
    const int g = lane >> 2, t4 = lane & 3;
    const float4 z4 = make_float4(0.f, 0.f, 0.f, 0.f);

    const bool m_live = (m0 + warp_m * 32) < SEQ;

    float acc[2][4][4];
    float4 pa[2], pb[2];

    // ======== Phase A: S = Q K^T * scale + logw (two 128x128 n-halves) ========
    const float scale = 0.08838834764831845f;   // 1/sqrt(128)
#pragma unroll 1
    for (int nt2 = 0; nt2 < 2; ++nt2) {
        const int n0 = nt2 * 128;
        const bool live = m_live && ((n0 + warp_n * 32) < SEQ);
#pragma unroll
        for (int mt = 0; mt < 2; mt++)
#pragma unroll
            for (int nt = 0; nt < 4; nt++)
#pragma unroll
                for (int e = 0; e < 4; e++) acc[mt][nt][e] = 0.f;

        {
            int gk = c4 * 4;
#pragma unroll
            for (int it = 0; it < 2; ++it) {
                int am = m0 + it * 64 + r_ld;
                int bn = n0 + it * 64 + r_ld;
                pa[it] = (am < SEQ) ? *(const float4*)(Q + (size_t)am * DMODEL + gk) : z4;
                pb[it] = (bn < SEQ) ? *(const float4*)(Kp + (size_t)bn * DMODEL + gk) : z4;
            }
            stage_store512(sm, pa, pb, r_ld, c4);
        }
        __syncthreads();

        for (int c = 0; c < 4; ++c) {          // DK=128 -> 4 chunks
            if (c + 1 < 4) {
                int gk = (c + 1) * KCHUNK + c4 * 4;
#pragma unroll
                for (int it = 0; it < 2; ++it) {
                    int am = m0 + it * 64 + r_ld;
                    int bn = n0 + it * 64 + r_ld;
                    pa[it] = (am < SEQ) ? *(const float4*)(Q + (size_t)am * DMODEL + gk) : z4;
                    pb[it] = (bn < SEQ) ? *(const float4*)(Kp + (size_t)bn * DMODEL + gk) : z4;
                }
            }
            if (live)
                mma_chunk512(smb + (uint32_t)(c & 1) * BUFSZ, acc, warp_m, warp_n, sub, i8);
            if (c + 1 < 4)
                stage_store512(sm + ((c + 1) & 1) * BUFSZ, pa, pb, r_ld, c4);
            __syncthreads();
        }

        // epilogue -> sS (+logw)
#pragma unroll
        for (int mt = 0; mt < 2; ++mt) {
            int rl = warp_m * 32 + mt * 16 + g;        // local row 0..127
            int m = m0 + rl;
#pragma unroll
            for (int nt = 0; nt < 4; ++nt) {
                int col = n0 + warp_n * 32 + nt * 8 + 2 * t4;
                float* d = acc[mt][nt];
                if (col < SEQ) {
                    bool mok = (m < SEQ);
                    float l0 = mok ? LW[(size_t)m * SEQ + col] : 0.f;
                    float l1 = mok ? LW[(size_t)m * SEQ + col + 1] : 0.f;
                    *(float2*)&sS[(size_t)rl * SSTRIDE + col] =
                        make_float2(fmaf(d[0], scale, l0), fmaf(d[1], scale, l1));
                    bool m8 = (m + 8 < SEQ);
                    float l2 = m8 ? LW[(size_t)(m + 8) * SEQ + col] : 0.f;
                    float l3 = m8 ? LW[(size_t)(m + 8) * SEQ + col + 1] : 0.f;
                    *(float2*)&sS[(size_t)(rl + 8) * SSTRIDE + col] =
                        make_float2(fmaf(d[2], scale, l2), fmaf(d[3], scale, l3));
                }
            }
        }
        __syncthreads();
    }

    // ======== Phase B: softmax rows in SMEM (16 warps x 8 rows) ========
    {
#pragma unroll 1
        for (int j = 0; j < 8; ++j) {
            int r = w * 8 + j;
            float* row = sS + (size_t)r * SSTRIDE;
            float x[7];
            float mx = -1e30f;
#pragma unroll
            for (int i = 0; i < 7; ++i) {
                int cidx = lane + i * 32;
                x[i] = (cidx < SEQ) ? row[cidx] : -1e30f;
                mx = fmaxf(mx, x[i]);
            }
#pragma unroll
            for (int o = 16; o > 0; o >>= 1) mx = fmaxf(mx, __shfl_xor_sync(0xffffffffu, mx, o));
            float sum = 0.f;
#pragma unroll
            for (int i = 0; i < 7; ++i) {
                x[i] = expf(x[i] - mx);
                sum += x[i];
            }
#pragma unroll
            for (int o = 16; o > 0; o >>= 1) sum += __shfl_xor_sync(0xffffffffu, sum, o);
            float inv = 1.0f / sum;
#pragma unroll
            for (int i = 0; i < 7; ++i) {
                int cidx = lane + i * 32;
                if (cidx < SEQ) row[cidx] = x[i] * inv;
            }
            if (lane < 28) row[SEQ + lane] = 0.f;     // zero pad cols 196..223
        }
    }
    __syncthreads();

    // ======== Phase C: ctx = P @ V^T (output 128x128, n = DK dense) ========
#pragma unroll
    for (int mt = 0; mt < 2; mt++)
#pragma unroll
        for (int nt = 0; nt < 4; nt++)
#pragma unroll
            for (int e = 0; e < 4; e++) acc[mt][nt][e] = 0.f;

    const int nchunkC = 7;                        // ceil(196/32)
    {
        int gk = c4 * 4;
#pragma unroll
        for (int it = 0; it < 2; ++it) {
            int rr = it * 64 + r_ld;
            pa[it] = *(const float4*)(sS + (size_t)rr * SSTRIDE + gk);
            pb[it] = *(const float4*)(Vt + (size_t)rr * SEQ + gk);
        }
        stage_store512(sm, pa, pb, r_ld, c4);
    }
    __syncthreads();

    for (int c = 0; c < nchunkC; ++c) {
        if (c + 1 < nchunkC) {
            int gk = (c + 1) * KCHUNK + c4 * 4;
            bool kok = gk < SEQ;
#pragma unroll
            for (int it = 0; it < 2; ++it) {
                int rr = it * 64 + r_ld;
                pa[it] = *(const float4*)(sS + (size_t)rr * SSTRIDE + gk);   // pad zeroed
                pb[it] = kok ? *(const float4*)(Vt + (size_t)rr * SEQ + gk) : z4;
            }
        }
        if (m_live)
            mma_chunk512(smb + (uint32_t)(c & 1) * BUFSZ, acc, warp_m, warp_n, sub, i8);
        if (c + 1 < nchunkC)
            stage_store512(sm + ((c + 1) & 1) * BUFSZ, pa, pb, r_ld, c4);
        __syncthreads();
    }

    // epilogue -> g_ctx
    float* C = g_ctx + (size_t)b * SEQ * DMODEL + h * DK;
#pragma unroll
    for (int mt = 0; mt < 2; ++mt) {
        int m = m0 + warp_m * 32 + mt * 16 + g;
#pragma unroll
        for (int nt = 0; nt < 4; ++nt) {
            int col = warp_n * 32 + nt * 8 + 2 * t4;
            float* d = acc[mt][nt];
            if (m < SEQ)
                *(float2*)(C + (size_t)m * DMODEL + col) = make_float2(d[0], d[1]);
            if (m + 8 < SEQ)
                *(float2*)(C + (size_t)(m + 8) * DMODEL + col) = make_float2(d[2], d[3]);
        }
    }
}

// ---------------- V transpose: g_vT[bh][n][k] = g_v[b][k][h*DK+n] ----------------
__global__ void vT_kernel()
{
    __shared__ float t[32][33];
    int bh = blockIdx.z;
    int b = bh >> 3, h = bh & 7;
    int k0 = blockIdx.x * 32, n0 = blockIdx.y * 32;
    int tx = threadIdx.x, ty = threadIdx.y;   // 32 x 8
#pragma unroll
    for (int j = 0; j < 4; ++j) {
        int k = k0 + ty + j * 8;
        t[ty + j * 8][tx] = (k < SEQ)
            ? g_v[((size_t)b * SEQ + k) * DMODEL + h * DK + n0 + tx] : 0.f;
    }
    __syncthreads();
#pragma unroll
    for (int j = 0; j < 4; ++j) {
        int n = n0 + ty + j * 8;
        int k = k0 + tx;
        if (k < SEQ)
            g_vT[(size_t)bh * DK * SEQ + (size_t)n * SEQ + k] = t[tx][ty + j * 8];
    }
}

// ---------------- geometry embedding -> logw[b,h,n,m] ----------------
__global__ void logw_kernel(const float* __restrict__ boxes,
                            const float* __restrict__ WGw,
                            const float* __restrict__ WGb)
{
    __shared__ float sW[8][64];
    __shared__ float sB[8];
    __shared__ float sbn[4];
    int t = threadIdx.x;
    int b = blockIdx.x / SEQ;
    int n = blockIdx.x % SEQ;

    for (int i = t; i < 512; i += blockDim.x) sW[i >> 6][i & 63] = WGw[i];
    if (t < 8) sB[t] = WGb[t];
    if (t == 0) {
        const float* bp = boxes + ((size_t)b * SEQ + n) * 4;
        float xmn = bp[0], ymn = bp[1], xmx = bp[2], ymx = bp[3];
        sbn[0] = (xmn + xmx) * 0.5f;
        sbn[1] = (ymn + ymx) * 0.5f;
        sbn[2] = (xmx - xmn) + 1.0f;
        sbn[3] = (ymx - ymn) + 1.0f;
    }
    __syncthreads();

    int m = t;
    if (m >= SEQ) return;

    const float* bm = boxes + ((size_t)b * SEQ + m) * 4;
    float xmn = bm[0], ymn = bm[1], xmx = bm[2], ymx = bm[3];
    float cxm = (xmn + xmx) * 0.5f, cym = (ymn + ymx) * 0.5f;
    float wm = (xmx - xmn) + 1.0f, hm = (ymx - ymn) + 1.0f;
    float cxn = sbn[0], cyn = sbn[1], wn = sbn[2], hn = sbn[3];

    float pos[4];
    pos[0] = logf(fmaxf(fabsf((cxn - cxm) / wn), 1e-3f));
    pos[1] = logf(fmaxf(fabsf((cyn - cym) / hn), 1e-3f));
    pos[2] = logf(wn / wm);
    pos[3] = logf(hn / hm);

    float acc[8];
#pragma unroll
    for (int h = 0; h < 8; h++) acc[h] = sB[h];

#pragma unroll
    for (int c = 0; c < 4; c++) {
        float p = 100.0f * pos[c];
#pragma unroll
        for (int j = 0; j < 8; j++) {
            float s, co;
            __sincosf(p * c_dim[j], &s, &co);
            int f = c * 8 + j;
#pragma unroll
            for (int h = 0; h < 8; h++)
                acc[h] += s * sW[h][f] + co * sW[h][f + 32];
        }
    }

    size_t base = ((size_t)b * HEADS) * SEQ * SEQ + (size_t)n * SEQ + m;
#pragma unroll
    for (int h = 0; h < 8; h++) {
        float wg = fmaxf(acc[h], 1e-6f);
        g_logw[base + (size_t)h * SEQ * SEQ] = logf(wg);
    }
}

// ---------------- launch ----------------
extern "C" void kernel_launch(void* const* d_in, const int* in_sizes, int n_in,
                              void* d_out, int out_size)
{
    const float* xq  = (const float*)d_in[0];
    const float* xk  = (const float*)d_in[1];
    const float* xv  = (const float*)d_in[2];
    const float* box = (const float*)d_in[3];
    const float* Wq  = (const float*)d_in[4];
    const float* bq  = (const float*)d_in[5];
    const float* Wk  = (const float*)d_in[6];
    const float* bk  = (const float*)d_in[7];
    const float* Wv  = (const float*)d_in[8];
    const float* bv  = (const float*)d_in[9];
    const float* Wo  = (const float*)d_in[10];
    const float* bo  = (const float*)d_in[11];
    const float* WGw = (const float*)d_in[12];
    const float* WGb = (const float*)d_in[13];
    float* out = (float*)d_out;

    cudaFuncSetAttribute(qkv_mma,    cudaFuncAttributeMaxDynamicSharedMemorySize, PSMEM);
    cudaFuncSetAttribute(out_mma,    cudaFuncAttributeMaxDynamicSharedMemorySize, PSMEM);
    cudaFuncSetAttribute(fused_attn, cudaFuncAttributeMaxDynamicSharedMemorySize, SMEM_FUSED);

    // 1) Q/K/V projections (fp16x2 MMA)
    qkv_mma<<<dim3(DMODEL / 128, MROWS / 128, 3), 256, PSMEM>>>(
        xq, xk, xv, Wq, Wk, Wv, bq, bk, bv);

    // 2) transpose V per head
    vT_kernel<<<dim3(7, 4, BATCH * HEADS), dim3(32, 8)>>>();

    // 3) geometry relation log-weights
    logw_kernel<<<BATCH * SEQ, 224>>>(box, WGw, WGb);

    // 4) fused: S = QK^T/sqrt(dk)+logw -> softmax -> P@V  (bf16x3, unchanged)
    fused_attn<<<dim3(2, BATCH * HEADS), 512, SMEM_FUSED>>>();

    // 5) output projection into d_out (fp16x2 MMA)
    out_mma<<<dim3(DMODEL / 128, MROWS / 128, 1), 256, PSMEM>>>(Wo, bo, out);
}

// round 13
// speedup vs baseline: 1.3347x; 1.0095x over previous
#include <cuda_runtime.h>
#include <cuda_bf16.h>
#include <cuda_fp16.h>
#include <math.h>
#include <stdint.h>

#define BATCH 32
#define SEQ 196
#define DMODEL 1024
#define HEADS 8
#define DK 128
#define MROWS (BATCH*SEQ)            // 6272

// ---------------- scratch (static device arrays; no allocations) ----------------
__device__ float g_q[MROWS*DMODEL];
__device__ float g_k[MROWS*DMODEL];
__device__ float g_v[MROWS*DMODEL];
__device__ float g_ctx[MROWS*DMODEL];
__device__ float g_vT[(size_t)BATCH*HEADS*DK*SEQ];      // [bh][n][k] transposed V
__device__ float g_logw[(size_t)BATCH*HEADS*SEQ*SEQ];   // geometry log-weights

__constant__ float c_dim[8] = {
    1.0f, 0.4216965034285822f, 0.1778279410038923f, 0.07498942093324558f,
    0.03162277660168379f, 0.013335214321633241f, 0.005623413251903491f,
    0.0023713737056616554f
};

// ============================================================================
// common helpers
// ============================================================================
__device__ __forceinline__ uint32_t smem_u32(const void* p) {
    uint32_t a;
    asm("{ .reg .u64 t; cvta.to.shared.u64 t, %1; cvt.u32.u64 %0, t; }" : "=r"(a) : "l"(p));
    return a;
}

__device__ __forceinline__ void ldsm4(uint32_t r[4], uint32_t addr) {
    asm volatile("ldmatrix.sync.aligned.m8n8.x4.shared.b16 {%0,%1,%2,%3}, [%4];"
        : "=r"(r[0]), "=r"(r[1]), "=r"(r[2]), "=r"(r[3]) : "r"(addr));
}

// fp16 MMA
__device__ __forceinline__ void mma16816h(float d[4], const uint32_t a[4], const uint32_t b[2]) {
    asm volatile("mma.sync.aligned.m16n8k16.row.col.f32.f16.f16.f32 "
        "{%0,%1,%2,%3}, {%4,%5,%6,%7}, {%8,%9}, {%0,%1,%2,%3};"
        : "+f"(d[0]), "+f"(d[1]), "+f"(d[2]), "+f"(d[3])
        : "r"(a[0]), "r"(a[1]), "r"(a[2]), "r"(a[3]), "r"(b[0]), "r"(b[1]));
}

// fp16 hi/lo split (A side; residual exact to ~2^-22)
__device__ __forceinline__ void split4h(float4 v, uint2& hi, uint2& lo) {
    __half2 h0 = __floats2half2_rn(v.x, v.y);
    __half2 h1 = __floats2half2_rn(v.z, v.w);
    __half2 l0 = __floats2half2_rn(v.x - __low2float(h0), v.y - __high2float(h0));
    __half2 l1 = __floats2half2_rn(v.z - __low2float(h1), v.w - __high2float(h1));
    hi = make_uint2(*(uint32_t*)&h0, *(uint32_t*)&h1);
    lo = make_uint2(*(uint32_t*)&l0, *(uint32_t*)&l1);
}

// fp16 plain convert (B side)
__device__ __forceinline__ uint2 cvt4h(float4 v) {
    __half2 h0 = __floats2half2_rn(v.x, v.y);
    __half2 h1 = __floats2half2_rn(v.z, v.w);
    return make_uint2(*(uint32_t*)&h0, *(uint32_t*)&h1);
}

// ============================================================================
// projection GEMM (fp16x2): Y[M,1024] = X[M,1024] @ W[1024,1024]^T + bias
// 256 threads, 8 warps (4m x 2n), warp tile 32x64, KCHUNK=32 — R12 config.
// ============================================================================
#define PKC 32
#define PNCH (DMODEL / PKC)          // 32
#define PGS 80                       // 32 fp16 = 64B + 16B pad
#define PA_HI 0
#define PA_LO (128*PGS)              // 10240
#define PB_HI (2*128*PGS)            // 20480
#define PBUF  (3*128*PGS)            // 30720
#define PSMEM (2*PBUF)               // 61440

__device__ __forceinline__ void stage_store_p(char* bp, const float4 pa[4],
                                              const float4 pb[4], int r_ld, int c4)
{
#pragma unroll
    for (int it = 0; it < 4; ++it) {
        uint32_t off = (uint32_t)(it * 32 + r_ld) * PGS + c4 * 8;
        uint2 hi, lo;
        split4h(pa[it], hi, lo);
        *(uint2*)(bp + PA_HI + off) = hi;
        *(uint2*)(bp + PA_LO + off) = lo;
        *(uint2*)(bp + PB_HI + off) = cvt4h(pb[it]);
    }
}

__device__ __forceinline__ void mma_chunk_p(uint32_t base, float acc[2][8][4],
                                            int warp_m, int warp_n, int sub, int i8)
{
#pragma unroll
    for (int ks = 0; ks < 2; ++ks) {
        const int kofs = ks * 16;
        uint32_t aHi[2][4], aLo[2][4];
#pragma unroll
        for (int mt = 0; mt < 2; ++mt) {
            int row = warp_m * 32 + mt * 16 + (sub & 1) * 8 + i8;
            int col = kofs + (sub >> 1) * 8;
            uint32_t ad = base + PA_HI + (uint32_t)row * PGS + col * 2;
            ldsm4(aHi[mt], ad);
            ldsm4(aLo[mt], ad + (PA_LO - PA_HI));
        }
#pragma unroll
        for (int ntp = 0; ntp < 4; ++ntp) {
            int nr = warp_n * 64 + ntp * 16 + (sub >> 1) * 8 + i8;
            int nc = kofs + (sub & 1) * 8;
            uint32_t bd = base + PB_HI + (uint32_t)nr * PGS + nc * 2;
            uint32_t bH[4];
            ldsm4(bH, bd);
#pragma unroll
            for (int mt = 0; mt < 2; ++mt) {
#pragma unroll
                for (int nh = 0; nh < 2; ++nh) {
                    float* d = acc[mt][ntp * 2 + nh];
                    mma16816h(d, aHi[mt], &bH[nh * 2]);
                    mma16816h(d, aLo[mt], &bH[nh * 2]);
                }
            }
        }
    }
}

__device__ __forceinline__ void fp16x2_gemm(const float* __restrict__ X,
                                            const float* __restrict__ W,
                                            const float* __restrict__ bias,
                                            float* __restrict__ Y)
{
    extern __shared__ __align__(16) char sm[];
    const uint32_t smb = smem_u32(sm);
    const int tid = threadIdx.x;
    const int lane = tid & 31, w = tid >> 5;
    const int warp_m = w & 3, warp_n = w >> 2;
    const int m0 = blockIdx.y * 128, n0 = blockIdx.x * 128;
    const int r_ld = tid >> 3, c4 = tid & 7;
    const int sub = lane >> 3, i8 = lane & 7;

    float acc[2][8][4];
#pragma unroll
    for (int mt = 0; mt < 2; mt++)
#pragma unroll
        for (int nt = 0; nt < 8; nt++)
#pragma unroll
            for (int e = 0; e < 4; e++) acc[mt][nt][e] = 0.f;

    float4 pa[4], pb[4];

    {
        const float* Ag = X + c4 * 4;
        const float* Bg = W + c4 * 4;
#pragma unroll
        for (int it = 0; it < 4; ++it) {
            pa[it] = *(const float4*)(Ag + (size_t)(m0 + it * 32 + r_ld) * DMODEL);
            pb[it] = *(const float4*)(Bg + (size_t)(n0 + it * 32 + r_ld) * DMODEL);
        }
        stage_store_p(sm, pa, pb, r_ld, c4);
    }
    __syncthreads();

    for (int c = 0; c < PNCH; ++c) {
        if (c + 1 < PNCH) {
            const int kc = (c + 1) * PKC;
            const float* Ag = X + kc + c4 * 4;
            const float* Bg = W + kc + c4 * 4;
#pragma unroll
            for (int it = 0; it < 4; ++it) {
                pa[it] = *(const float4*)(Ag + (size_t)(m0 + it * 32 + r_ld) * DMODEL);
                pb[it] = *(const float4*)(Bg + (size_t)(n0 + it * 32 + r_ld) * DMODEL);
            }
        }
        mma_chunk_p(smb + (uint32_t)(c & 1) * PBUF, acc, warp_m, warp_n, sub, i8);
        if (c + 1 < PNCH)
            stage_store_p(sm + ((c + 1) & 1) * PBUF, pa, pb, r_ld, c4);
        __syncthreads();
    }

    const int g = lane >> 2, t4 = lane & 3;
#pragma unroll
    for (int mt = 0; mt < 2; ++mt) {
        int row = m0 + warp_m * 32 + mt * 16 + g;
#pragma unroll
        for (int nt = 0; nt < 8; ++nt) {
            int col = n0 + warp_n * 64 + nt * 8 + 2 * t4;
            float b0 = bias[col], b1 = bias[col + 1];
            float* d = acc[mt][nt];
            *(float2*)&Y[(size_t)row * DMODEL + col] = make_float2(d[0] + b0, d[1] + b1);
            *(float2*)&Y[(size_t)(row + 8) * DMODEL + col] = make_float2(d[2] + b0, d[3] + b1);
        }
    }
}

__global__ void __launch_bounds__(256, 1)
qkv_mma(const float* __restrict__ xq, const float* __restrict__ xk,
        const float* __restrict__ xv,
        const float* __restrict__ wq, const float* __restrict__ wk,
        const float* __restrict__ wv,
        const float* __restrict__ bq, const float* __restrict__ bk,
        const float* __restrict__ bv)
{
    int z = blockIdx.z;
    const float* X = (z == 0) ? xq : (z == 1) ? xk : xv;
    const float* W = (z == 0) ? wq : (z == 1) ? wk : wv;
    const float* bias = (z == 0) ? bq : (z == 1) ? bk : bv;
    float* Y = (z == 0) ? g_q : (z == 1) ? g_k : g_v;
    fp16x2_gemm(X, W, bias, Y);
}

__global__ void __launch_bounds__(256, 1)
out_mma(const float* __restrict__ Wo, const float* __restrict__ bo,
        float* __restrict__ Y)
{
    fp16x2_gemm(g_ctx, Wo, bo, Y);
}

// ============================================================================
// fused attention, 512 threads / 16 warps, warp tile 32x32, dead-tile skip.
// NOW fp16x2: A (Q / P) split hi/lo fp16, B (K / V) single fp16.
// ============================================================================
#define KCHUNK 32
#define FGS 80                       // 32 fp16 = 64B + 16B pad
#define F_AHI 0
#define F_ALO (128*FGS)              // 10240
#define F_BHI (2*128*FGS)            // 20480
#define FBUF  (3*128*FGS)            // 30720
#define SSTRIDE 224
#define SMEM_FUSED (2*FBUF + 128*SSTRIDE*4)   // 61440 + 114688 = 176128

// 512-thread staging: 2 float4 per thread; A split, B single fp16
__device__ __forceinline__ void stage_store512h(char* bp, const float4 pa[2],
                                                const float4 pb[2], int r_ld, int c4)
{
#pragma unroll
    for (int it = 0; it < 2; ++it) {
        uint32_t off = (uint32_t)(it * 64 + r_ld) * FGS + c4 * 8;
        uint2 hi, lo;
        split4h(pa[it], hi, lo);
        *(uint2*)(bp + F_AHI + off) = hi;
        *(uint2*)(bp + F_ALO + off) = lo;
        *(uint2*)(bp + F_BHI + off) = cvt4h(pb[it]);
    }
}

// one 32-K chunk, 16-warp layout (warp tile 32x32), fp16x2
__device__ __forceinline__ void mma_chunk512h(uint32_t base, float acc[2][4][4],
                                              int warp_m, int warp_n, int sub, int i8)
{
#pragma unroll
    for (int ks = 0; ks < 2; ++ks) {
        const int kofs = ks * 16;
        uint32_t aHi[2][4], aLo[2][4];
#pragma unroll
        for (int mt = 0; mt < 2; ++mt) {
            int row = warp_m * 32 + mt * 16 + (sub & 1) * 8 + i8;
            int col = kofs + (sub >> 1) * 8;
            uint32_t ad = base + F_AHI + (uint32_t)row * FGS + col * 2;
            ldsm4(aHi[mt], ad);
            ldsm4(aLo[mt], ad + (F_ALO - F_AHI));
        }
#pragma unroll
        for (int ntp = 0; ntp < 2; ++ntp) {
            int nr = warp_n * 32 + ntp * 16 + (sub >> 1) * 8 + i8;
            int nc = kofs + (sub & 1) * 8;
            uint32_t bd = base + F_BHI + (uint32_t)nr * FGS + nc * 2;
            uint32_t bH[4];
            ldsm4(bH, bd);
#pragma unroll
            for (int mt = 0; mt < 2; ++mt) {
#pragma unroll
                for (int nh = 0; nh < 2; ++nh) {
                    float* d = acc[mt][ntp * 2 + nh];
                    mma16816h(d, aHi[mt], &bH[nh * 2]);
                    mma16816h(d, aLo[mt], &bH[nh * 2]);
                }
            }
        }
    }
}

__global__ void __launch_bounds__(512, 1)
fused_attn()
{
    extern __shared__ __align__(16) char sm[];
    const uint32_t smb = smem_u32(sm);
    float* sS = (float*)(sm + 2 * FBUF);         // 128 x SSTRIDE fp32

    const int bh = blockIdx.y;
    const int b = bh >> 3, h = bh & 7;
    const int m0 = blockIdx.x * 128;
    const float* Q  = g_q + (size_t)b * SEQ * DMODEL + h * DK;
    const float* Kp = g_k + (size_t)b * SEQ * DMODEL + h * DK;
    const float* LW = g_logw + (size_t)bh * SEQ * SEQ;
    const float* Vt = g_vT + (size_t)bh * DK * SEQ;

    const int tid = threadIdx.x;
    const int lane = tid & 31, w = tid >> 5;     // w: 0..15
    const int warp_m = w & 3, warp_n = w >> 2;   // 4 x 4 warp grid
    const int r_ld = tid >> 3, c4 = tid & 7;     // r_ld: 0..63
    const int sub = lane >> 3, i8 = lane & 7;
    const int g = lane >> 2, t4 = lane & 3;
    const float4 z4 = make_float4(0.f, 0.f, 0.f, 0.f);

    const bool m_live = (m0 + warp_m * 32) < SEQ;

    float acc[2][4][4];
    float4 pa[2], pb[2];

    // ======== Phase A: S = Q K^T * scale + logw (two 128x128 n-halves) ========
    const float scale = 0.08838834764831845f;   // 1/sqrt(128)
#pragma unroll 1
    for (int nt2 = 0; nt2 < 2; ++nt2) {
        const int n0 = nt2 * 128;
        const bool live = m_live && ((n0 + warp_n * 32) < SEQ);
#pragma unroll
        for (int mt = 0; mt < 2; mt++)
#pragma unroll
            for (int nt = 0; nt < 4; nt++)
#pragma unroll
                for (int e = 0; e < 4; e++) acc[mt][nt][e] = 0.f;

        {
            int gk = c4 * 4;
#pragma unroll
            for (int it = 0; it < 2; ++it) {
                int am = m0 + it * 64 + r_ld;
                int bn = n0 + it * 64 + r_ld;
                pa[it] = (am < SEQ) ? *(const float4*)(Q + (size_t)am * DMODEL + gk) : z4;
                pb[it] = (bn < SEQ) ? *(const float4*)(Kp + (size_t)bn * DMODEL + gk) : z4;
            }
            stage_store512h(sm, pa, pb, r_ld, c4);
        }
        __syncthreads();

        for (int c = 0; c < 4; ++c) {          // DK=128 -> 4 chunks
            if (c + 1 < 4) {
                int gk = (c + 1) * KCHUNK + c4 * 4;
#pragma unroll
                for (int it = 0; it < 2; ++it) {
                    int am = m0 + it * 64 + r_ld;
                    int bn = n0 + it * 64 + r_ld;
                    pa[it] = (am < SEQ) ? *(const float4*)(Q + (size_t)am * DMODEL + gk) : z4;
                    pb[it] = (bn < SEQ) ? *(const float4*)(Kp + (size_t)bn * DMODEL + gk) : z4;
                }
            }
            if (live)
                mma_chunk512h(smb + (uint32_t)(c & 1) * FBUF, acc, warp_m, warp_n, sub, i8);
            if (c + 1 < 4)
                stage_store512h(sm + ((c + 1) & 1) * FBUF, pa, pb, r_ld, c4);
            __syncthreads();
        }

        // epilogue -> sS (+logw)
#pragma unroll
        for (int mt = 0; mt < 2; ++mt) {
            int rl = warp_m * 32 + mt * 16 + g;        // local row 0..127
            int m = m0 + rl;
#pragma unroll
            for (int nt = 0; nt < 4; ++nt) {
                int col = n0 + warp_n * 32 + nt * 8 + 2 * t4;
                float* d = acc[mt][nt];
                if (col < SEQ) {
                    bool mok = (m < SEQ);
                    float l0 = mok ? LW[(size_t)m * SEQ + col] : 0.f;
                    float l1 = mok ? LW[(size_t)m * SEQ + col + 1] : 0.f;
                    *(float2*)&sS[(size_t)rl * SSTRIDE + col] =
                        make_float2(fmaf(d[0], scale, l0), fmaf(d[1], scale, l1));
                    bool m8 = (m + 8 < SEQ);
                    float l2 = m8 ? LW[(size_t)(m + 8) * SEQ + col] : 0.f;
                    float l3 = m8 ? LW[(size_t)(m + 8) * SEQ + col + 1] : 0.f;
                    *(float2*)&sS[(size_t)(rl + 8) * SSTRIDE + col] =
                        make_float2(fmaf(d[2], scale, l2), fmaf(d[3], scale, l3));
                }
            }
        }
        __syncthreads();
    }

    // ======== Phase B: softmax rows in SMEM (16 warps x 8 rows) ========
    {
#pragma unroll 1
        for (int j = 0; j < 8; ++j) {
            int r = w * 8 + j;
            float* row = sS + (size_t)r * SSTRIDE;
            float x[7];
            float mx = -1e30f;
#pragma unroll
            for (int i = 0; i < 7; ++i) {
                int cidx = lane + i * 32;
                x[i] = (cidx < SEQ) ? row[cidx] : -1e30f;
                mx = fmaxf(mx, x[i]);
            }
#pragma unroll
            for (int o = 16; o > 0; o >>= 1) mx = fmaxf(mx, __shfl_xor_sync(0xffffffffu, mx, o));
            float sum = 0.f;
#pragma unroll
            for (int i = 0; i < 7; ++i) {
                x[i] = expf(x[i] - mx);
                sum += x[i];
            }
#pragma unroll
            for (int o = 16; o > 0; o >>= 1) sum += __shfl_xor_sync(0xffffffffu, sum, o);
            float inv = 1.0f / sum;
#pragma unroll
            for (int i = 0; i < 7; ++i) {
                int cidx = lane + i * 32;
                if (cidx < SEQ) row[cidx] = x[i] * inv;
            }
            if (lane < 28) row[SEQ + lane] = 0.f;     // zero pad cols 196..223
        }
    }
    __syncthreads();

    // ======== Phase C: ctx = P @ V^T (output 128x128, n = DK dense) ========
#pragma unroll
    for (int mt = 0; mt < 2; mt++)
#pragma unroll
        for (int nt = 0; nt < 4; nt++)
#pragma unroll
            for (int e = 0; e < 4; e++) acc[mt][nt][e] = 0.f;

    const int nchunkC = 7;                        // ceil(196/32)
    {
        int gk = c4 * 4;
#pragma unroll
        for (int it = 0; it < 2; ++it) {
            int rr = it * 64 + r_ld;
            pa[it] = *(const float4*)(sS + (size_t)rr * SSTRIDE + gk);
            pb[it] = *(const float4*)(Vt + (size_t)rr * SEQ + gk);
        }
        stage_store512h(sm, pa, pb, r_ld, c4);
    }
    __syncthreads();

    for (int c = 0; c < nchunkC; ++c) {
        if (c + 1 < nchunkC) {
            int gk = (c + 1) * KCHUNK + c4 * 4;
            bool kok = gk < SEQ;
#pragma unroll
            for (int it = 0; it < 2; ++it) {
                int rr = it * 64 + r_ld;
                pa[it] = *(const float4*)(sS + (size_t)rr * SSTRIDE + gk);   // pad zeroed
                pb[it] = kok ? *(const float4*)(Vt + (size_t)rr * SEQ + gk) : z4;
            }
        }
        if (m_live)
            mma_chunk512h(smb + (uint32_t)(c & 1) * FBUF, acc, warp_m, warp_n, sub, i8);
        if (c + 1 < nchunkC)
            stage_store512h(sm + ((c + 1) & 1) * FBUF, pa, pb, r_ld, c4);
        __syncthreads();
    }

    // epilogue -> g_ctx
    float* C = g_ctx + (size_t)b * SEQ * DMODEL + h * DK;
#pragma unroll
    for (int mt = 0; mt < 2; ++mt) {
        int m = m0 + warp_m * 32 + mt * 16 + g;
#pragma unroll
        for (int nt = 0; nt < 4; ++nt) {
            int col = warp_n * 32 + nt * 8 + 2 * t4;
            float* d = acc[mt][nt];
            if (m < SEQ)
                *(float2*)(C + (size_t)m * DMODEL + col) = make_float2(d[0], d[1]);
            if (m + 8 < SEQ)
                *(float2*)(C + (size_t)(m + 8) * DMODEL + col) = make_float2(d[2], d[3]);
        }
    }
}

// ---------------- V transpose: g_vT[bh][n][k] = g_v[b][k][h*DK+n] ----------------
__global__ void vT_kernel()
{
    __shared__ float t[32][33];
    int bh = blockIdx.z;
    int b = bh >> 3, h = bh & 7;
    int k0 = blockIdx.x * 32, n0 = blockIdx.y * 32;
    int tx = threadIdx.x, ty = threadIdx.y;   // 32 x 8
#pragma unroll
    for (int j = 0; j < 4; ++j) {
        int k = k0 + ty + j * 8;
        t[ty + j * 8][tx] = (k < SEQ)
            ? g_v[((size_t)b * SEQ + k) * DMODEL + h * DK + n0 + tx] : 0.f;
    }
    __syncthreads();
#pragma unroll
    for (int j = 0; j < 4; ++j) {
        int n = n0 + ty + j * 8;
        int k = k0 + tx;
        if (k < SEQ)
            g_vT[(size_t)bh * DK * SEQ + (size_t)n * SEQ + k] = t[tx][ty + j * 8];
    }
}

// ---------------- geometry embedding -> logw[b,h,n,m] ----------------
__global__ void logw_kernel(const float* __restrict__ boxes,
                            const float* __restrict__ WGw,
                            const float* __restrict__ WGb)
{
    __shared__ float sW[8][64];
    __shared__ float sB[8];
    __shared__ float sbn[4];
    int t = threadIdx.x;
    int b = blockIdx.x / SEQ;
    int n = blockIdx.x % SEQ;

    for (int i = t; i < 512; i += blockDim.x) sW[i >> 6][i & 63] = WGw[i];
    if (t < 8) sB[t] = WGb[t];
    if (t == 0) {
        const float* bp = boxes + ((size_t)b * SEQ + n) * 4;
        float xmn = bp[0], ymn = bp[1], xmx = bp[2], ymx = bp[3];
        sbn[0] = (xmn + xmx) * 0.5f;
        sbn[1] = (ymn + ymx) * 0.5f;
        sbn[2] = (xmx - xmn) + 1.0f;
        sbn[3] = (ymx - ymn) + 1.0f;
    }
    __syncthreads();

    int m = t;
    if (m >= SEQ) return;

    const float* bm = boxes + ((size_t)b * SEQ + m) * 4;
    float xmn = bm[0], ymn = bm[1], xmx = bm[2], ymx = bm[3];
    float cxm = (xmn + xmx) * 0.5f, cym = (ymn + ymx) * 0.5f;
    float wm = (xmx - xmn) + 1.0f, hm = (ymx - ymn) + 1.0f;
    float cxn = sbn[0], cyn = sbn[1], wn = sbn[2], hn = sbn[3];

    float pos[4];
    pos[0] = logf(fmaxf(fabsf((cxn - cxm) / wn), 1e-3f));
    pos[1] = logf(fmaxf(fabsf((cyn - cym) / hn), 1e-3f));
    pos[2] = logf(wn / wm);
    pos[3] = logf(hn / hm);

    float acc[8];
#pragma unroll
    for (int h = 0; h < 8; h++) acc[h] = sB[h];

#pragma unroll
    for (int c = 0; c < 4; c++) {
        float p = 100.0f * pos[c];
#pragma unroll
        for (int j = 0; j < 8; j++) {
            float s, co;
            __sincosf(p * c_dim[j], &s, &co);
            int f = c * 8 + j;
#pragma unroll
            for (int h = 0; h < 8; h++)
                acc[h] += s * sW[h][f] + co * sW[h][f + 32];
        }
    }

    size_t base = ((size_t)b * HEADS) * SEQ * SEQ + (size_t)n * SEQ + m;
#pragma unroll
    for (int h = 0; h < 8; h++) {
        float wg = fmaxf(acc[h], 1e-6f);
        g_logw[base + (size_t)h * SEQ * SEQ] = logf(wg);
    }
}

// ---------------- launch ----------------
extern "C" void kernel_launch(void* const* d_in, const int* in_sizes, int n_in,
                              void* d_out, int out_size)
{
    const float* xq  = (const float*)d_in[0];
    const float* xk  = (const float*)d_in[1];
    const float* xv  = (const float*)d_in[2];
    const float* box = (const float*)d_in[3];
    const float* Wq  = (const float*)d_in[4];
    const float* bq  = (const float*)d_in[5];
    const float* Wk  = (const float*)d_in[6];
    const float* bk  = (const float*)d_in[7];
    const float* Wv  = (const float*)d_in[8];
    const float* bv  = (const float*)d_in[9];
    const float* Wo  = (const float*)d_in[10];
    const float* bo  = (const float*)d_in[11];
    const float* WGw = (const float*)d_in[12];
    const float* WGb = (const float*)d_in[13];
    float* out = (float*)d_out;

    cudaFuncSetAttribute(qkv_mma,    cudaFuncAttributeMaxDynamicSharedMemorySize, PSMEM);
    cudaFuncSetAttribute(out_mma,    cudaFuncAttributeMaxDynamicSharedMemorySize, PSMEM);
    cudaFuncSetAttribute(fused_attn, cudaFuncAttributeMaxDynamicSharedMemorySize, SMEM_FUSED);

    // 1) Q/K/V projections (fp16x2 MMA)
    qkv_mma<<<dim3(DMODEL / 128, MROWS / 128, 3), 256, PSMEM>>>(
        xq, xk, xv, Wq, Wk, Wv, bq, bk, bv);

    // 2) transpose V per head
    vT_kernel<<<dim3(7, 4, BATCH * HEADS), dim3(32, 8)>>>();

    // 3) geometry relation log-weights
    logw_kernel<<<BATCH * SEQ, 224>>>(box, WGw, WGb);

    // 4) fused: S = QK^T/sqrt(dk)+logw -> softmax -> P@V  (fp16x2)
    fused_attn<<<dim3(2, BATCH * HEADS), 512, SMEM_FUSED>>>();

    // 5) output projection into d_out (fp16x2 MMA)
    out_mma<<<dim3(DMODEL / 128, MROWS / 128, 1), 256, PSMEM>>>(Wo, bo, out);
}

// round 14
// speedup vs baseline: 1.3443x; 1.0072x over previous
#include <cuda_runtime.h>
#include <cuda_bf16.h>
#include <cuda_fp16.h>
#include <math.h>
#include <stdint.h>

#define BATCH 32
#define SEQ 196
#define DMODEL 1024
#define HEADS 8
#define DK 128
#define MROWS (BATCH*SEQ)            // 6272

// ---------------- scratch (static device arrays; no allocations) ----------------
__device__ __half g_qh[MROWS*DMODEL];                   // Q hi (fp16)
__device__ __half g_ql[MROWS*DMODEL];                   // Q lo (fp16 residual)
__device__ __half g_kh[MROWS*DMODEL];                   // K (fp16)
__device__ __half g_vh[MROWS*DMODEL];                   // V (fp16)
__device__ __half g_vTh[(size_t)BATCH*HEADS*DK*SEQ];    // V^T per head (fp16)
__device__ float  g_ctx[MROWS*DMODEL];
__device__ float  g_logw[(size_t)BATCH*HEADS*SEQ*SEQ];  // geometry log-weights

__constant__ float c_dim[8] = {
    1.0f, 0.4216965034285822f, 0.1778279410038923f, 0.07498942093324558f,
    0.03162277660168379f, 0.013335214321633241f, 0.005623413251903491f,
    0.0023713737056616554f
};

// ============================================================================
// common helpers
// ============================================================================
__device__ __forceinline__ uint32_t smem_u32(const void* p) {
    uint32_t a;
    asm("{ .reg .u64 t; cvta.to.shared.u64 t, %1; cvt.u32.u64 %0, t; }" : "=r"(a) : "l"(p));
    return a;
}

__device__ __forceinline__ void ldsm4(uint32_t r[4], uint32_t addr) {
    asm volatile("ldmatrix.sync.aligned.m8n8.x4.shared.b16 {%0,%1,%2,%3}, [%4];"
        : "=r"(r[0]), "=r"(r[1]), "=r"(r[2]), "=r"(r[3]) : "r"(addr));
}

__device__ __forceinline__ void mma16816h(float d[4], const uint32_t a[4], const uint32_t b[2]) {
    asm volatile("mma.sync.aligned.m16n8k16.row.col.f32.f16.f16.f32 "
        "{%0,%1,%2,%3}, {%4,%5,%6,%7}, {%8,%9}, {%0,%1,%2,%3};"
        : "+f"(d[0]), "+f"(d[1]), "+f"(d[2]), "+f"(d[3])
        : "r"(a[0]), "r"(a[1]), "r"(a[2]), "r"(a[3]), "r"(b[0]), "r"(b[1]));
}

// fp16 hi/lo split (residual exact to ~2^-22)
__device__ __forceinline__ void split4h(float4 v, uint2& hi, uint2& lo) {
    __half2 h0 = __floats2half2_rn(v.x, v.y);
    __half2 h1 = __floats2half2_rn(v.z, v.w);
    __half2 l0 = __floats2half2_rn(v.x - __low2float(h0), v.y - __high2float(h0));
    __half2 l1 = __floats2half2_rn(v.z - __low2float(h1), v.w - __high2float(h1));
    hi = make_uint2(*(uint32_t*)&h0, *(uint32_t*)&h1);
    lo = make_uint2(*(uint32_t*)&l0, *(uint32_t*)&l1);
}

__device__ __forceinline__ uint2 cvt4h(float4 v) {
    __half2 h0 = __floats2half2_rn(v.x, v.y);
    __half2 h1 = __floats2half2_rn(v.z, v.w);
    return make_uint2(*(uint32_t*)&h0, *(uint32_t*)&h1);
}

// ============================================================================
// projection GEMM (fp16x2): 256 threads, 8 warps (4m x 2n), warp tile 32x64.
// EPI 0: Y fp32 (+bias)  | EPI 1: hi/lo fp16 -> Yh,Yl | EPI 2: single fp16 -> Yh
// ============================================================================
#define PKC 32
#define PNCH (DMODEL / PKC)          // 32
#define PGS 80                       // 32 fp16 = 64B + 16B pad
#define PA_HI 0
#define PA_LO (128*PGS)              // 10240
#define PB_HI (2*128*PGS)            // 20480
#define PBUF  (3*128*PGS)            // 30720
#define PSMEM (2*PBUF)               // 61440

__device__ __forceinline__ void stage_store_p(char* bp, const float4 pa[4],
                                              const float4 pb[4], int r_ld, int c4)
{
#pragma unroll
    for (int it = 0; it < 4; ++it) {
        uint32_t off = (uint32_t)(it * 32 + r_ld) * PGS + c4 * 8;
        uint2 hi, lo;
        split4h(pa[it], hi, lo);
        *(uint2*)(bp + PA_HI + off) = hi;
        *(uint2*)(bp + PA_LO + off) = lo;
        *(uint2*)(bp + PB_HI + off) = cvt4h(pb[it]);
    }
}

__device__ __forceinline__ void mma_chunk_p(uint32_t base, float acc[2][8][4],
                                            int warp_m, int warp_n, int sub, int i8)
{
#pragma unroll
    for (int ks = 0; ks < 2; ++ks) {
        const int kofs = ks * 16;
        uint32_t aHi[2][4], aLo[2][4];
#pragma unroll
        for (int mt = 0; mt < 2; ++mt) {
            int row = warp_m * 32 + mt * 16 + (sub & 1) * 8 + i8;
            int col = kofs + (sub >> 1) * 8;
            uint32_t ad = base + PA_HI + (uint32_t)row * PGS + col * 2;
            ldsm4(aHi[mt], ad);
            ldsm4(aLo[mt], ad + (PA_LO - PA_HI));
        }
#pragma unroll
        for (int ntp = 0; ntp < 4; ++ntp) {
            int nr = warp_n * 64 + ntp * 16 + (sub >> 1) * 8 + i8;
            int nc = kofs + (sub & 1) * 8;
            uint32_t bd = base + PB_HI + (uint32_t)nr * PGS + nc * 2;
            uint32_t bH[4];
            ldsm4(bH, bd);
#pragma unroll
            for (int mt = 0; mt < 2; ++mt) {
#pragma unroll
                for (int nh = 0; nh < 2; ++nh) {
                    float* d = acc[mt][ntp * 2 + nh];
                    mma16816h(d, aHi[mt], &bH[nh * 2]);
                    mma16816h(d, aLo[mt], &bH[nh * 2]);
                }
            }
        }
    }
}

__device__ __forceinline__ void epi_write_h(float v0, float v1, __half* Yh, __half* Yl,
                                            size_t idx, bool wlo)
{
    __half2 h = __floats2half2_rn(v0, v1);
    *(uint32_t*)&Yh[idx] = *(uint32_t*)&h;
    if (wlo) {
        __half2 l = __floats2half2_rn(v0 - __low2float(h), v1 - __high2float(h));
        *(uint32_t*)&Yl[idx] = *(uint32_t*)&l;
    }
}

template<int EPI>
__device__ __forceinline__ void fp16x2_gemm(const float* __restrict__ X,
                                            const float* __restrict__ W,
                                            const float* __restrict__ bias,
                                            float* __restrict__ Y,
                                            __half* __restrict__ Yh,
                                            __half* __restrict__ Yl)
{
    extern __shared__ __align__(16) char sm[];
    const uint32_t smb = smem_u32(sm);
    const int tid = threadIdx.x;
    const int lane = tid & 31, w = tid >> 5;
    const int warp_m = w & 3, warp_n = w >> 2;
    const int m0 = blockIdx.y * 128, n0 = blockIdx.x * 128;
    const int r_ld = tid >> 3, c4 = tid & 7;
    const int sub = lane >> 3, i8 = lane & 7;

    float acc[2][8][4];
#pragma unroll
    for (int mt = 0; mt < 2; mt++)
#pragma unroll
        for (int nt = 0; nt < 8; nt++)
#pragma unroll
            for (int e = 0; e < 4; e++) acc[mt][nt][e] = 0.f;

    float4 pa[4], pb[4];

    {
        const float* Ag = X + c4 * 4;
        const float* Bg = W + c4 * 4;
#pragma unroll
        for (int it = 0; it < 4; ++it) {
            pa[it] = *(const float4*)(Ag + (size_t)(m0 + it * 32 + r_ld) * DMODEL);
            pb[it] = *(const float4*)(Bg + (size_t)(n0 + it * 32 + r_ld) * DMODEL);
        }
        stage_store_p(sm, pa, pb, r_ld, c4);
    }
    __syncthreads();

    for (int c = 0; c < PNCH; ++c) {
        if (c + 1 < PNCH) {
            const int kc = (c + 1) * PKC;
            const float* Ag = X + kc + c4 * 4;
            const float* Bg = W + kc + c4 * 4;
#pragma unroll
            for (int it = 0; it < 4; ++it) {
                pa[it] = *(const float4*)(Ag + (size_t)(m0 + it * 32 + r_ld) * DMODEL);
                pb[it] = *(const float4*)(Bg + (size_t)(n0 + it * 32 + r_ld) * DMODEL);
            }
        }
        mma_chunk_p(smb + (uint32_t)(c & 1) * PBUF, acc, warp_m, warp_n, sub, i8);
        if (c + 1 < PNCH)
            stage_store_p(sm + ((c + 1) & 1) * PBUF, pa, pb, r_ld, c4);
        __syncthreads();
    }

    const int g = lane >> 2, t4 = lane & 3;
#pragma unroll
    for (int mt = 0; mt < 2; ++mt) {
        int row = m0 + warp_m * 32 + mt * 16 + g;
#pragma unroll
        for (int nt = 0; nt < 8; ++nt) {
            int col = n0 + warp_n * 64 + nt * 8 + 2 * t4;
            float b0 = bias[col], b1 = bias[col + 1];
            float* d = acc[mt][nt];
            float v0 = d[0] + b0, v1 = d[1] + b1;
            float v2 = d[2] + b0, v3 = d[3] + b1;
            size_t i0 = (size_t)row * DMODEL + col;
            size_t i1 = (size_t)(row + 8) * DMODEL + col;
            if (EPI == 0) {
                *(float2*)&Y[i0] = make_float2(v0, v1);
                *(float2*)&Y[i1] = make_float2(v2, v3);
            } else {
                epi_write_h(v0, v1, Yh, Yl, i0, EPI == 1);
                epi_write_h(v2, v3, Yh, Yl, i1, EPI == 1);
            }
        }
    }
}

__global__ void __launch_bounds__(256, 1)
qkv_mma(const float* __restrict__ xq, const float* __restrict__ xk,
        const float* __restrict__ xv,
        const float* __restrict__ wq, const float* __restrict__ wk,
        const float* __restrict__ wv,
        const float* __restrict__ bq, const float* __restrict__ bk,
        const float* __restrict__ bv)
{
    int z = blockIdx.z;
    if (z == 0)      fp16x2_gemm<1>(xq, wq, bq, nullptr, g_qh, g_ql);
    else if (z == 1) fp16x2_gemm<2>(xk, wk, bk, nullptr, g_kh, nullptr);
    else             fp16x2_gemm<2>(xv, wv, bv, nullptr, g_vh, nullptr);
}

__global__ void __launch_bounds__(256, 1)
out_mma(const float* __restrict__ Wo, const float* __restrict__ bo,
        float* __restrict__ Y)
{
    fp16x2_gemm<0>(g_ctx, Wo, bo, Y, nullptr, nullptr);
}

// ============================================================================
// fused attention, 512 threads / 16 warps, warp tile 32x32, dead-tile skip.
// fp16x2; Q/K pre-converted (pure LDG->STS staging), P split in-kernel.
// ============================================================================
#define KCHUNK 32
#define FGS 80                       // 32 fp16 = 64B + 16B pad
#define F_AHI 0
#define F_ALO (128*FGS)              // 10240
#define F_BHI (2*128*FGS)            // 20480
#define FBUF  (3*128*FGS)            // 30720
#define SSTRIDE 224
#define SMEM_FUSED (2*FBUF + 128*SSTRIDE*4)   // 61440 + 114688 = 176128

// Phase A staging: pre-converted fp16, 3 uint2 per thread per it
__device__ __forceinline__ void stage_storeA(char* bp, const uint2 qh[2],
                                             const uint2 ql[2], const uint2 kh[2],
                                             int r_ld, int c4)
{
#pragma unroll
    for (int it = 0; it < 2; ++it) {
        uint32_t off = (uint32_t)(it * 64 + r_ld) * FGS + c4 * 8;
        *(uint2*)(bp + F_AHI + off) = qh[it];
        *(uint2*)(bp + F_ALO + off) = ql[it];
        *(uint2*)(bp + F_BHI + off) = kh[it];
    }
}

// Phase C staging: P fp32 split in-kernel, V pre-converted
__device__ __forceinline__ void stage_storeC(char* bp, const float4 pa[2],
                                             const uint2 vb[2], int r_ld, int c4)
{
#pragma unroll
    for (int it = 0; it < 2; ++it) {
        uint32_t off = (uint32_t)(it * 64 + r_ld) * FGS + c4 * 8;
        uint2 hi, lo;
        split4h(pa[it], hi, lo);
        *(uint2*)(bp + F_AHI + off) = hi;
        *(uint2*)(bp + F_ALO + off) = lo;
        *(uint2*)(bp + F_BHI + off) = vb[it];
    }
}

__device__ __forceinline__ void mma_chunk512h(uint32_t base, float acc[2][4][4],
                                              int warp_m, int warp_n, int sub, int i8)
{
#pragma unroll
    for (int ks = 0; ks < 2; ++ks) {
        const int kofs = ks * 16;
        uint32_t aHi[2][4], aLo[2][4];
#pragma unroll
        for (int mt = 0; mt < 2; ++mt) {
            int row = warp_m * 32 + mt * 16 + (sub & 1) * 8 + i8;
            int col = kofs + (sub >> 1) * 8;
            uint32_t ad = base + F_AHI + (uint32_t)row * FGS + col * 2;
            ldsm4(aHi[mt], ad);
            ldsm4(aLo[mt], ad + (F_ALO - F_AHI));
        }
#pragma unroll
        for (int ntp = 0; ntp < 2; ++ntp) {
            int nr = warp_n * 32 + ntp * 16 + (sub >> 1) * 8 + i8;
            int nc = kofs + (sub & 1) * 8;
            uint32_t bd = base + F_BHI + (uint32_t)nr * FGS + nc * 2;
            uint32_t bH[4];
            ldsm4(bH, bd);
#pragma unroll
            for (int mt = 0; mt < 2; ++mt) {
#pragma unroll
                for (int nh = 0; nh < 2; ++nh) {
                    float* d = acc[mt][ntp * 2 + nh];
                    mma16816h(d, aHi[mt], &bH[nh * 2]);
                    mma16816h(d, aLo[mt], &bH[nh * 2]);
                }
            }
        }
    }
}

__global__ void __launch_bounds__(512, 1)
fused_attn()
{
    extern __shared__ __align__(16) char sm[];
    const uint32_t smb = smem_u32(sm);
    float* sS = (float*)(sm + 2 * FBUF);         // 128 x SSTRIDE fp32

    const int bh = blockIdx.y;
    const int b = bh >> 3, h = bh & 7;
    const int m0 = blockIdx.x * 128;
    const __half* Qh = g_qh + (size_t)b * SEQ * DMODEL + h * DK;
    const __half* Ql = g_ql + (size_t)b * SEQ * DMODEL + h * DK;
    const __half* Kh = g_kh + (size_t)b * SEQ * DMODEL + h * DK;
    const float*  LW = g_logw + (size_t)bh * SEQ * SEQ;
    const __half* Vt = g_vTh + (size_t)bh * DK * SEQ;

    const int tid = threadIdx.x;
    const int lane = tid & 31, w = tid >> 5;     // w: 0..15
    const int warp_m = w & 3, warp_n = w >> 2;   // 4 x 4 warp grid
    const int r_ld = tid >> 3, c4 = tid & 7;     // r_ld: 0..63
    const int sub = lane >> 3, i8 = lane & 7;
    const int g = lane >> 2, t4 = lane & 3;
    const uint2 uz = make_uint2(0u, 0u);

    const bool m_live = (m0 + warp_m * 32) < SEQ;

    float acc[2][4][4];

    // ======== Phase A: S = Q K^T * scale + logw (two 128x128 n-halves) ========
    const float scale = 0.08838834764831845f;   // 1/sqrt(128)
    uint2 qh2[2], ql2[2], kh2[2];
#pragma unroll 1
    for (int nt2 = 0; nt2 < 2; ++nt2) {
        const int n0 = nt2 * 128;
        const bool live = m_live && ((n0 + warp_n * 32) < SEQ);
#pragma unroll
        for (int mt = 0; mt < 2; mt++)
#pragma unroll
            for (int nt = 0; nt < 4; nt++)
#pragma unroll
                for (int e = 0; e < 4; e++) acc[mt][nt][e] = 0.f;

        {
            int gk = c4 * 4;
#pragma unroll
            for (int it = 0; it < 2; ++it) {
                int am = m0 + it * 64 + r_ld;
                int bn = n0 + it * 64 + r_ld;
                qh2[it] = (am < SEQ) ? *(const uint2*)(Qh + (size_t)am * DMODEL + gk) : uz;
                ql2[it] = (am < SEQ) ? *(const uint2*)(Ql + (size_t)am * DMODEL + gk) : uz;
                kh2[it] = (bn < SEQ) ? *(const uint2*)(Kh + (size_t)bn * DMODEL + gk) : uz;
            }
            stage_storeA(sm, qh2, ql2, kh2, r_ld, c4);
        }
        __syncthreads();

        for (int c = 0; c < 4; ++c) {          // DK=128 -> 4 chunks
            if (c + 1 < 4) {
                int gk = (c + 1) * KCHUNK + c4 * 4;
#pragma unroll
                for (int it = 0; it < 2; ++it) {
                    int am = m0 + it * 64 + r_ld;
                    int bn = n0 + it * 64 + r_ld;
                    qh2[it] = (am < SEQ) ? *(const uint2*)(Qh + (size_t)am * DMODEL + gk) : uz;
                    ql2[it] = (am < SEQ) ? *(const uint2*)(Ql + (size_t)am * DMODEL + gk) : uz;
                    kh2[it] = (bn < SEQ) ? *(const uint2*)(Kh + (size_t)bn * DMODEL + gk) : uz;
                }
            }
            if (live)
                mma_chunk512h(smb + (uint32_t)(c & 1) * FBUF, acc, warp_m, warp_n, sub, i8);
            if (c + 1 < 4)
                stage_storeA(sm + ((c + 1) & 1) * FBUF, qh2, ql2, kh2, r_ld, c4);
            __syncthreads();
        }

        // epilogue -> sS (+logw)
#pragma unroll
        for (int mt = 0; mt < 2; ++mt) {
            int rl = warp_m * 32 + mt * 16 + g;        // local row 0..127
            int m = m0 + rl;
#pragma unroll
            for (int nt = 0; nt < 4; ++nt) {
                int col = n0 + warp_n * 32 + nt * 8 + 2 * t4;
                float* d = acc[mt][nt];
                if (col < SEQ) {
                    bool mok = (m < SEQ);
                    float l0 = mok ? LW[(size_t)m * SEQ + col] : 0.f;
                    float l1 = mok ? LW[(size_t)m * SEQ + col + 1] : 0.f;
                    *(float2*)&sS[(size_t)rl * SSTRIDE + col] =
                        make_float2(fmaf(d[0], scale, l0), fmaf(d[1], scale, l1));
                    bool m8 = (m + 8 < SEQ);
                    float l2 = m8 ? LW[(size_t)(m + 8) * SEQ + col] : 0.f;
                    float l3 = m8 ? LW[(size_t)(m + 8) * SEQ + col + 1] : 0.f;
                    *(float2*)&sS[(size_t)(rl + 8) * SSTRIDE + col] =
                        make_float2(fmaf(d[2], scale, l2), fmaf(d[3], scale, l3));
                }
            }
        }
        __syncthreads();
    }

    // ======== Phase B: softmax rows in SMEM (16 warps x 8 rows) ========
    {
#pragma unroll 1
        for (int j = 0; j < 8; ++j) {
            int r = w * 8 + j;
            float* row = sS + (size_t)r * SSTRIDE;
            float x[7];
            float mx = -1e30f;
#pragma unroll
            for (int i = 0; i < 7; ++i) {
                int cidx = lane + i * 32;
                x[i] = (cidx < SEQ) ? row[cidx] : -1e30f;
                mx = fmaxf(mx, x[i]);
            }
#pragma unroll
            for (int o = 16; o > 0; o >>= 1) mx = fmaxf(mx, __shfl_xor_sync(0xffffffffu, mx, o));
            float sum = 0.f;
#pragma unroll
            for (int i = 0; i < 7; ++i) {
                x[i] = expf(x[i] - mx);
                sum += x[i];
            }
#pragma unroll
            for (int o = 16; o > 0; o >>= 1) sum += __shfl_xor_sync(0xffffffffu, sum, o);
            float inv = 1.0f / sum;
#pragma unroll
            for (int i = 0; i < 7; ++i) {
                int cidx = lane + i * 32;
                if (cidx < SEQ) row[cidx] = x[i] * inv;
            }
            if (lane < 28) row[SEQ + lane] = 0.f;     // zero pad cols 196..223
        }
    }
    __syncthreads();

    // ======== Phase C: ctx = P @ V^T (output 128x128, n = DK dense) ========
#pragma unroll
    for (int mt = 0; mt < 2; mt++)
#pragma unroll
        for (int nt = 0; nt < 4; nt++)
#pragma unroll
            for (int e = 0; e < 4; e++) acc[mt][nt][e] = 0.f;

    const int nchunkC = 7;                        // ceil(196/32)
    float4 pc[2];
    uint2 vb[2];
    {
        int gk = c4 * 4;
#pragma unroll
        for (int it = 0; it < 2; ++it) {
            int rr = it * 64 + r_ld;
            pc[it] = *(const float4*)(sS + (size_t)rr * SSTRIDE + gk);
            vb[it] = *(const uint2*)(Vt + (size_t)rr * SEQ + gk);
        }
        stage_storeC(sm, pc, vb, r_ld, c4);
    }
    __syncthreads();

    for (int c = 0; c < nchunkC; ++c) {
        if (c + 1 < nchunkC) {
            int gk = (c + 1) * KCHUNK + c4 * 4;
            bool kok = gk < SEQ;
#pragma unroll
            for (int it = 0; it < 2; ++it) {
                int rr = it * 64 + r_ld;
                pc[it] = *(const float4*)(sS + (size_t)rr * SSTRIDE + gk);   // pad zeroed
                vb[it] = kok ? *(const uint2*)(Vt + (size_t)rr * SEQ + gk) : uz;
            }
        }
        if (m_live)
            mma_chunk512h(smb + (uint32_t)(c & 1) * FBUF, acc, warp_m, warp_n, sub, i8);
        if (c + 1 < nchunkC)
            stage_storeC(sm + ((c + 1) & 1) * FBUF, pc, vb, r_ld, c4);
        __syncthreads();
    }

    // epilogue -> g_ctx
    float* C = g_ctx + (size_t)b * SEQ * DMODEL + h * DK;
#pragma unroll
    for (int mt = 0; mt < 2; ++mt) {
        int m = m0 + warp_m * 32 + mt * 16 + g;
#pragma unroll
        for (int nt = 0; nt < 4; ++nt) {
            int col = warp_n * 32 + nt * 8 + 2 * t4;
            float* d = acc[mt][nt];
            if (m < SEQ)
                *(float2*)(C + (size_t)m * DMODEL + col) = make_float2(d[0], d[1]);
            if (m + 8 < SEQ)
                *(float2*)(C + (size_t)(m + 8) * DMODEL + col) = make_float2(d[2], d[3]);
        }
    }
}

// ---------------- V transpose (fp16): g_vTh[bh][n][k] = g_vh[b][k][h*DK+n] ----------------
__global__ void vT_kernel()
{
    __shared__ __half t[32][40];
    int bh = blockIdx.z;
    int b = bh >> 3, h = bh & 7;
    int k0 = blockIdx.x * 32, n0 = blockIdx.y * 32;
    int tx = threadIdx.x, ty = threadIdx.y;   // 32 x 8
#pragma unroll
    for (int j = 0; j < 4; ++j) {
        int k = k0 + ty + j * 8;
        t[ty + j * 8][tx] = (k < SEQ)
            ? g_vh[((size_t)b * SEQ + k) * DMODEL + h * DK + n0 + tx] : __half(0.f);
    }
    __syncthreads();
#pragma unroll
    for (int j = 0; j < 4; ++j) {
        int n = n0 + ty + j * 8;
        int k = k0 + tx;
        if (k < SEQ)
            g_vTh[(size_t)bh * DK * SEQ + (size_t)n * SEQ + k] = t[tx][ty + j * 8];
    }
}

// ---------------- geometry embedding -> logw[b,h,n,m] ----------------
__global__ void logw_kernel(const float* __restrict__ boxes,
                            const float* __restrict__ WGw,
                            const float* __restrict__ WGb)
{
    __shared__ float sW[8][64];
    __shared__ float sB[8];
    __shared__ float sbn[4];
    int t = threadIdx.x;
    int b = blockIdx.x / SEQ;
    int n = blockIdx.x % SEQ;

    for (int i = t; i < 512; i += blockDim.x) sW[i >> 6][i & 63] = WGw[i];
    if (t < 8) sB[t] = WGb[t];
    if (t == 0) {
        const float* bp = boxes + ((size_t)b * SEQ + n) * 4;
        float xmn = bp[0], ymn = bp[1], xmx = bp[2], ymx = bp[3];
        sbn[0] = (xmn + xmx) * 0.5f;
        sbn[1] = (ymn + ymx) * 0.5f;
        sbn[2] = (xmx - xmn) + 1.0f;
        sbn[3] = (ymx - ymn) + 1.0f;
    }
    __syncthreads();

    int m = t;
    if (m >= SEQ) return;

    const float* bm = boxes + ((size_t)b * SEQ + m) * 4;
    float xmn = bm[0], ymn = bm[1], xmx = bm[2], ymx = bm[3];
    float cxm = (xmn + xmx) * 0.5f, cym = (ymn + ymx) * 0.5f;
    float wm = (xmx - xmn) + 1.0f, hm = (ymx - ymn) + 1.0f;
    float cxn = sbn[0], cyn = sbn[1], wn = sbn[2], hn = sbn[3];

    float pos[4];
    pos[0] = logf(fmaxf(fabsf((cxn - cxm) / wn), 1e-3f));
    pos[1] = logf(fmaxf(fabsf((cyn - cym) / hn), 1e-3f));
    pos[2] = logf(wn / wm);
    pos[3] = logf(hn / hm);

    float acc[8];
#pragma unroll
    for (int h = 0; h < 8; h++) acc[h] = sB[h];

#pragma unroll
    for (int c = 0; c < 4; c++) {
        float p = 100.0f * pos[c];
#pragma unroll
        for (int j = 0; j < 8; j++) {
            float s, co;
            __sincosf(p * c_dim[j], &s, &co);
            int f = c * 8 + j;
#pragma unroll
            for (int h = 0; h < 8; h++)
                acc[h] += s * sW[h][f] + co * sW[h][f + 32];
        }
    }

    size_t base = ((size_t)b * HEADS) * SEQ * SEQ + (size_t)n * SEQ + m;
#pragma unroll
    for (int h = 0; h < 8; h++) {
        float wg = fmaxf(acc[h], 1e-6f);
        g_logw[base + (size_t)h * SEQ * SEQ] = logf(wg);
    }
}

// ---------------- launch ----------------
extern "C" void kernel_launch(void* const* d_in, const int* in_sizes, int n_in,
                              void* d_out, int out_size)
{
    const float* xq  = (const float*)d_in[0];
    const float* xk  = (const float*)d_in[1];
    const float* xv  = (const float*)d_in[2];
    const float* box = (const float*)d_in[3];
    const float* Wq  = (const float*)d_in[4];
    const float* bq  = (const float*)d_in[5];
    const float* Wk  = (const float*)d_in[6];
    const float* bk  = (const float*)d_in[7];
    const float* Wv  = (const float*)d_in[8];
    const float* bv  = (const float*)d_in[9];
    const float* Wo  = (const float*)d_in[10];
    const float* bo  = (const float*)d_in[11];
    const float* WGw = (const float*)d_in[12];
    const float* WGb = (const float*)d_in[13];
    float* out = (float*)d_out;

    cudaFuncSetAttribute(qkv_mma,    cudaFuncAttributeMaxDynamicSharedMemorySize, PSMEM);
    cudaFuncSetAttribute(out_mma,    cudaFuncAttributeMaxDynamicSharedMemorySize, PSMEM);
    cudaFuncSetAttribute(fused_attn, cudaFuncAttributeMaxDynamicSharedMemorySize, SMEM_FUSED);

    // 1) Q/K/V projections (fp16x2 MMA; epilogues emit fp16 operands)
    qkv_mma<<<dim3(DMODEL / 128, MROWS / 128, 3), 256, PSMEM>>>(
        xq, xk, xv, Wq, Wk, Wv, bq, bk, bv);

    // 2) transpose V per head (fp16)
    vT_kernel<<<dim3(7, 4, BATCH * HEADS), dim3(32, 8)>>>();

    // 3) geometry relation log-weights
    logw_kernel<<<BATCH * SEQ, 224>>>(box, WGw, WGb);

    // 4) fused: S = QK^T/sqrt(dk)+logw -> softmax -> P@V  (fp16x2, pre-converted)
    fused_attn<<<dim3(2, BATCH * HEADS), 512, SMEM_FUSED>>>();

    // 5) output projection into d_out (fp16x2 MMA)
    out_mma<<<dim3(DMODEL / 128, MROWS / 128, 1), 256, PSMEM>>>(Wo, bo, out);
}

// round 16
// speedup vs baseline: 1.3547x; 1.0077x over previous
#include <cuda_runtime.h>
#include <cuda_bf16.h>
#include <cuda_fp16.h>
#include <math.h>
#include <stdint.h>

#define BATCH 32
#define SEQ 196
#define DMODEL 1024
#define HEADS 8
#define DK 128
#define MROWS (BATCH*SEQ)            // 6272

// ---------------- scratch (static device arrays; no allocations) ----------------
__device__ __half g_qh[MROWS*DMODEL];                   // Q (fp16)
__device__ __half g_kh[MROWS*DMODEL];                   // K (fp16)
__device__ __half g_vh[MROWS*DMODEL];                   // V (fp16)
__device__ __half g_vTh[(size_t)BATCH*HEADS*DK*SEQ];    // V^T per head (fp16)
__device__ __half g_ctxh[MROWS*DMODEL];                 // ctx hi (fp16)
__device__ __half g_ctxl[MROWS*DMODEL];                 // ctx lo (fp16 residual)
__device__ float  g_logw[(size_t)BATCH*HEADS*SEQ*SEQ];  // geometry log-weights

__constant__ float c_dim[8] = {
    1.0f, 0.4216965034285822f, 0.1778279410038923f, 0.07498942093324558f,
    0.03162277660168379f, 0.013335214321633241f, 0.005623413251903491f,
    0.0023713737056616554f
};

// ============================================================================
// common helpers
// ============================================================================
__device__ __forceinline__ uint32_t smem_u32(const void* p) {
    uint32_t a;
    asm("{ .reg .u64 t; cvta.to.shared.u64 t, %1; cvt.u32.u64 %0, t; }" : "=r"(a) : "l"(p));
    return a;
}

__device__ __forceinline__ void ldsm4(uint32_t r[4], uint32_t addr) {
    asm volatile("ldmatrix.sync.aligned.m8n8.x4.shared.b16 {%0,%1,%2,%3}, [%4];"
        : "=r"(r[0]), "=r"(r[1]), "=r"(r[2]), "=r"(r[3]) : "r"(addr));
}

__device__ __forceinline__ void mma16816h(float d[4], const uint32_t a[4], const uint32_t b[2]) {
    asm volatile("mma.sync.aligned.m16n8k16.row.col.f32.f16.f16.f32 "
        "{%0,%1,%2,%3}, {%4,%5,%6,%7}, {%8,%9}, {%0,%1,%2,%3};"
        : "+f"(d[0]), "+f"(d[1]), "+f"(d[2]), "+f"(d[3])
        : "r"(a[0]), "r"(a[1]), "r"(a[2]), "r"(a[3]), "r"(b[0]), "r"(b[1]));
}

// fp16 hi/lo split (residual exact to ~2^-22)
__device__ __forceinline__ void split4h(float4 v, uint2& hi, uint2& lo) {
    __half2 h0 = __floats2half2_rn(v.x, v.y);
    __half2 h1 = __floats2half2_rn(v.z, v.w);
    __half2 l0 = __floats2half2_rn(v.x - __low2float(h0), v.y - __high2float(h0));
    __half2 l1 = __floats2half2_rn(v.z - __low2float(h1), v.w - __high2float(h1));
    hi = make_uint2(*(uint32_t*)&h0, *(uint32_t*)&h1);
    lo = make_uint2(*(uint32_t*)&l0, *(uint32_t*)&l1);
}

__device__ __forceinline__ uint2 cvt4h(float4 v) {
    __half2 h0 = __floats2half2_rn(v.x, v.y);
    __half2 h1 = __floats2half2_rn(v.z, v.w);
    return make_uint2(*(uint32_t*)&h0, *(uint32_t*)&h1);
}

// ============================================================================
// projection GEMM (fp16x2 accuracy on A): 256 threads, 8 warps, warp tile 32x64.
// ============================================================================
#define PKC 32
#define PNCH (DMODEL / PKC)          // 32
#define PGS 80                       // 32 fp16 = 64B + 16B pad
#define PA_HI 0
#define PA_LO (128*PGS)              // 10240
#define PB_HI (2*128*PGS)            // 20480
#define PBUF  (3*128*PGS)            // 30720
#define PSMEM (2*PBUF)               // 61440

__device__ __forceinline__ void mma_chunk_p(uint32_t base, float acc[2][8][4],
                                            int warp_m, int warp_n, int sub, int i8)
{
#pragma unroll
    for (int ks = 0; ks < 2; ++ks) {
        const int kofs = ks * 16;
        uint32_t aHi[2][4], aLo[2][4];
#pragma unroll
        for (int mt = 0; mt < 2; ++mt) {
            int row = warp_m * 32 + mt * 16 + (sub & 1) * 8 + i8;
            int col = kofs + (sub >> 1) * 8;
            uint32_t ad = base + PA_HI + (uint32_t)row * PGS + col * 2;
            ldsm4(aHi[mt], ad);
            ldsm4(aLo[mt], ad + (PA_LO - PA_HI));
        }
#pragma unroll
        for (int ntp = 0; ntp < 4; ++ntp) {
            int nr = warp_n * 64 + ntp * 16 + (sub >> 1) * 8 + i8;
            int nc = kofs + (sub & 1) * 8;
            uint32_t bd = base + PB_HI + (uint32_t)nr * PGS + nc * 2;
            uint32_t bH[4];
            ldsm4(bH, bd);
#pragma unroll
            for (int mt = 0; mt < 2; ++mt) {
#pragma unroll
                for (int nh = 0; nh < 2; ++nh) {
                    float* d = acc[mt][ntp * 2 + nh];
                    mma16816h(d, aHi[mt], &bH[nh * 2]);
                    mma16816h(d, aLo[mt], &bH[nh * 2]);
                }
            }
        }
    }
}

// PRE_A = 0: X fp32, split in staging. PRE_A = 1: Ah/Al pre-split fp16.
// EPI 0: fp32 Y (+bias). EPI 2: single fp16 -> Yh.
template<int PRE_A, int EPI>
__device__ __forceinline__ void fp16x2_gemm(const float* __restrict__ X,
                                            const __half* __restrict__ Ah,
                                            const __half* __restrict__ Al,
                                            const float* __restrict__ W,
                                            const float* __restrict__ bias,
                                            float* __restrict__ Y,
                                            __half* __restrict__ Yh)
{
    extern __shared__ __align__(16) char sm[];
    const uint32_t smb = smem_u32(sm);
    const int tid = threadIdx.x;
    const int lane = tid & 31, w = tid >> 5;
    const int warp_m = w & 3, warp_n = w >> 2;
    const int m0 = blockIdx.y * 128, n0 = blockIdx.x * 128;
    const int r_ld = tid >> 3, c4 = tid & 7;
    const int sub = lane >> 3, i8 = lane & 7;

    float acc[2][8][4];
#pragma unroll
    for (int mt = 0; mt < 2; mt++)
#pragma unroll
        for (int nt = 0; nt < 8; nt++)
#pragma unroll
            for (int e = 0; e < 4; e++) acc[mt][nt][e] = 0.f;

    float4 pa[4], pb[4];
    uint2 ah[4], al[4];

    auto ldg = [&](int kc) {
        int gk = kc + c4 * 4;
#pragma unroll
        for (int it = 0; it < 4; ++it) {
            size_t rowA = (size_t)(m0 + it * 32 + r_ld) * DMODEL + gk;
            if (PRE_A) {
                ah[it] = *(const uint2*)(Ah + rowA);
                al[it] = *(const uint2*)(Al + rowA);
            } else {
                pa[it] = *(const float4*)(X + rowA);
            }
            pb[it] = *(const float4*)(W + (size_t)(n0 + it * 32 + r_ld) * DMODEL + gk);
        }
    };
    auto sts = [&](char* bp) {
#pragma unroll
        for (int it = 0; it < 4; ++it) {
            uint32_t off = (uint32_t)(it * 32 + r_ld) * PGS + c4 * 8;
            if (PRE_A) {
                *(uint2*)(bp + PA_HI + off) = ah[it];
                *(uint2*)(bp + PA_LO + off) = al[it];
            } else {
                uint2 hi, lo;
                split4h(pa[it], hi, lo);
                *(uint2*)(bp + PA_HI + off) = hi;
                *(uint2*)(bp + PA_LO + off) = lo;
            }
            *(uint2*)(bp + PB_HI + off) = cvt4h(pb[it]);
        }
    };

    ldg(0);
    sts(sm);
    __syncthreads();

    for (int c = 0; c < PNCH; ++c) {
        if (c + 1 < PNCH) ldg((c + 1) * PKC);
        mma_chunk_p(smb + (uint32_t)(c & 1) * PBUF, acc, warp_m, warp_n, sub, i8);
        if (c + 1 < PNCH) sts(sm + ((c + 1) & 1) * PBUF);
        __syncthreads();
    }

    const int g = lane >> 2, t4 = lane & 3;
#pragma unroll
    for (int mt = 0; mt < 2; ++mt) {
        int row = m0 + warp_m * 32 + mt * 16 + g;
#pragma unroll
        for (int nt = 0; nt < 8; ++nt) {
            int col = n0 + warp_n * 64 + nt * 8 + 2 * t4;
            float b0 = bias[col], b1 = bias[col + 1];
            float* d = acc[mt][nt];
            float v0 = d[0] + b0, v1 = d[1] + b1;
            float v2 = d[2] + b0, v3 = d[3] + b1;
            size_t i0 = (size_t)row * DMODEL + col;
            size_t i1 = (size_t)(row + 8) * DMODEL + col;
            if (EPI == 0) {
                *(float2*)&Y[i0] = make_float2(v0, v1);
                *(float2*)&Y[i1] = make_float2(v2, v3);
            } else {
                __half2 h0 = __floats2half2_rn(v0, v1);
                __half2 h1 = __floats2half2_rn(v2, v3);
                *(uint32_t*)&Yh[i0] = *(uint32_t*)&h0;
                *(uint32_t*)&Yh[i1] = *(uint32_t*)&h1;
            }
        }
    }
}

__global__ void __launch_bounds__(256, 1)
qkv_mma(const float* __restrict__ xq, const float* __restrict__ xk,
        const float* __restrict__ xv,
        const float* __restrict__ wq, const float* __restrict__ wk,
        const float* __restrict__ wv,
        const float* __restrict__ bq, const float* __restrict__ bk,
        const float* __restrict__ bv)
{
    int z = blockIdx.z;
    if (z == 0)      fp16x2_gemm<0,2>(xq, nullptr, nullptr, wq, bq, nullptr, g_qh);
    else if (z == 1) fp16x2_gemm<0,2>(xk, nullptr, nullptr, wk, bk, nullptr, g_kh);
    else             fp16x2_gemm<0,2>(xv, nullptr, nullptr, wv, bv, nullptr, g_vh);
}

__global__ void __launch_bounds__(256, 1)
out_mma(const float* __restrict__ Wo, const float* __restrict__ bo,
        float* __restrict__ Y)
{
    fp16x2_gemm<1,0>(nullptr, g_ctxh, g_ctxl, Wo, bo, Y, nullptr);
}

// ============================================================================
// fused attention, 512 threads / 16 warps, warp tile 32x32, dead-tile skip.
// Single-fp16 A (Q / P) x single-fp16 B (K / V): 16 MMAs per chunk per warp.
// ctx emitted as fp16 hi/lo for the out projection.
// ============================================================================
#define KCHUNK 32
#define FGS 80                       // 32 fp16 = 64B + 16B pad
#define F_AHI 0
#define F_BHI (128*FGS)              // 10240
#define FBUF  (2*128*FGS)            // 20480
#define SSTRIDE 224
#define SMEM_FUSED (2*FBUF + 128*SSTRIDE*4)   // 40960 + 114688 = 155648

__device__ __forceinline__ void stage_storeAB(char* bp, const uint2 a2[2],
                                              const uint2 b2[2], int r_ld, int c4)
{
#pragma unroll
    for (int it = 0; it < 2; ++it) {
        uint32_t off = (uint32_t)(it * 64 + r_ld) * FGS + c4 * 8;
        *(uint2*)(bp + F_AHI + off) = a2[it];
        *(uint2*)(bp + F_BHI + off) = b2[it];
    }
}

// one 32-K chunk, 16-warp layout (warp tile 32x32), single-fp16 A and B
__device__ __forceinline__ void mma_chunk512s(uint32_t base, float acc[2][4][4],
                                              int warp_m, int warp_n, int sub, int i8)
{
#pragma unroll
    for (int ks = 0; ks < 2; ++ks) {
        const int kofs = ks * 16;
        uint32_t aH[2][4];
#pragma unroll
        for (int mt = 0; mt < 2; ++mt) {
            int row = warp_m * 32 + mt * 16 + (sub & 1) * 8 + i8;
            int col = kofs + (sub >> 1) * 8;
            ldsm4(aH[mt], base + F_AHI + (uint32_t)row * FGS + col * 2);
        }
#pragma unroll
        for (int ntp = 0; ntp < 2; ++ntp) {
            int nr = warp_n * 32 + ntp * 16 + (sub >> 1) * 8 + i8;
            int nc = kofs + (sub & 1) * 8;
            uint32_t bH[4];
            ldsm4(bH, base + F_BHI + (uint32_t)nr * FGS + nc * 2);
#pragma unroll
            for (int mt = 0; mt < 2; ++mt) {
#pragma unroll
                for (int nh = 0; nh < 2; ++nh)
                    mma16816h(acc[mt][ntp * 2 + nh], aH[mt], &bH[nh * 2]);
            }
        }
    }
}

__global__ void __launch_bounds__(512, 1)
fused_attn()
{
    extern __shared__ __align__(16) char sm[];
    const uint32_t smb = smem_u32(sm);
    float* sS = (float*)(sm + 2 * FBUF);         // 128 x SSTRIDE fp32

    const int bh = blockIdx.y;
    const int b = bh >> 3, h = bh & 7;
    const int m0 = blockIdx.x * 128;
    const __half* Qh = g_qh + (size_t)b * SEQ * DMODEL + h * DK;
    const __half* Kh = g_kh + (size_t)b * SEQ * DMODEL + h * DK;
    const float*  LW = g_logw + (size_t)bh * SEQ * SEQ;
    const __half* Vt = g_vTh + (size_t)bh * DK * SEQ;

    const int tid = threadIdx.x;
    const int lane = tid & 31, w = tid >> 5;     // w: 0..15
    const int warp_m = w & 3, warp_n = w >> 2;   // 4 x 4 warp grid
    const int r_ld = tid >> 3, c4 = tid & 7;     // r_ld: 0..63
    const int sub = lane >> 3, i8 = lane & 7;
    const int g = lane >> 2, t4 = lane & 3;
    const uint2 uz = make_uint2(0u, 0u);

    const bool m_live = (m0 + warp_m * 32) < SEQ;

    float acc[2][4][4];
    uint2 a2[2], b2[2];

    // ======== Phase A: S = Q K^T * scale + logw (two 128x128 n-halves) ========
    const float scale = 0.08838834764831845f;   // 1/sqrt(128)
#pragma unroll 1
    for (int nt2 = 0; nt2 < 2; ++nt2) {
        const int n0 = nt2 * 128;
        const bool live = m_live && ((n0 + warp_n * 32) < SEQ);
#pragma unroll
        for (int mt = 0; mt < 2; mt++)
#pragma unroll
            for (int nt = 0; nt < 4; nt++)
#pragma unroll
                for (int e = 0; e < 4; e++) acc[mt][nt][e] = 0.f;

        {
            int gk = c4 * 4;
#pragma unroll
            for (int it = 0; it < 2; ++it) {
                int am = m0 + it * 64 + r_ld;
                int bn = n0 + it * 64 + r_ld;
                a2[it] = (am < SEQ) ? *(const uint2*)(Qh + (size_t)am * DMODEL + gk) : uz;
                b2[it] = (bn < SEQ) ? *(const uint2*)(Kh + (size_t)bn * DMODEL + gk) : uz;
            }
            stage_storeAB(sm, a2, b2, r_ld, c4);
        }
        __syncthreads();

        for (int c = 0; c < 4; ++c) {          // DK=128 -> 4 chunks
            if (c + 1 < 4) {
                int gk = (c + 1) * KCHUNK + c4 * 4;
#pragma unroll
                for (int it = 0; it < 2; ++it) {
                    int am = m0 + it * 64 + r_ld;
                    int bn = n0 + it * 64 + r_ld;
                    a2[it] = (am < SEQ) ? *(const uint2*)(Qh + (size_t)am * DMODEL + gk) : uz;
                    b2[it] = (bn < SEQ) ? *(const uint2*)(Kh + (size_t)bn * DMODEL + gk) : uz;
                }
            }
            if (live)
                mma_chunk512s(smb + (uint32_t)(c & 1) * FBUF, acc, warp_m, warp_n, sub, i8);
            if (c + 1 < 4)
                stage_storeAB(sm + ((c + 1) & 1) * FBUF, a2, b2, r_ld, c4);
            __syncthreads();
        }

        // epilogue -> sS (+logw)
#pragma unroll
        for (int mt = 0; mt < 2; ++mt) {
            int rl = warp_m * 32 + mt * 16 + g;        // local row 0..127
            int m = m0 + rl;
#pragma unroll
            for (int nt = 0; nt < 4; ++nt) {
                int col = n0 + warp_n * 32 + nt * 8 + 2 * t4;
                float* d = acc[mt][nt];
                if (col < SEQ) {
                    bool mok = (m < SEQ);
                    float l0 = mok ? LW[(size_t)m * SEQ + col] : 0.f;
                    float l1 = mok ? LW[(size_t)m * SEQ + col + 1] : 0.f;
                    *(float2*)&sS[(size_t)rl * SSTRIDE + col] =
                        make_float2(fmaf(d[0], scale, l0), fmaf(d[1], scale, l1));
                    bool m8 = (m + 8 < SEQ);
                    float l2 = m8 ? LW[(size_t)(m + 8) * SEQ + col] : 0.f;
                    float l3 = m8 ? LW[(size_t)(m + 8) * SEQ + col + 1] : 0.f;
                    *(float2*)&sS[(size_t)(rl + 8) * SSTRIDE + col] =
                        make_float2(fmaf(d[2], scale, l2), fmaf(d[3], scale, l3));
                }
            }
        }
        __syncthreads();
    }

    // ======== Phase B: softmax rows in SMEM (16 warps x 8 rows) ========
    {
#pragma unroll 1
        for (int j = 0; j < 8; ++j) {
            int r = w * 8 + j;
            float* row = sS + (size_t)r * SSTRIDE;
            float x[7];
            float mx = -1e30f;
#pragma unroll
            for (int i = 0; i < 7; ++i) {
                int cidx = lane + i * 32;
                x[i] = (cidx < SEQ) ? row[cidx] : -1e30f;
                mx = fmaxf(mx, x[i]);
            }
#pragma unroll
            for (int o = 16; o > 0; o >>= 1) mx = fmaxf(mx, __shfl_xor_sync(0xffffffffu, mx, o));
            float sum = 0.f;
#pragma unroll
            for (int i = 0; i < 7; ++i) {
                x[i] = expf(x[i] - mx);
                sum += x[i];
            }
#pragma unroll
            for (int o = 16; o > 0; o >>= 1) sum += __shfl_xor_sync(0xffffffffu, sum, o);
            float inv = 1.0f / sum;
#pragma unroll
            for (int i = 0; i < 7; ++i) {
                int cidx = lane + i * 32;
                if (cidx < SEQ) row[cidx] = x[i] * inv;
            }
            if (lane < 28) row[SEQ + lane] = 0.f;     // zero pad cols 196..223
        }
    }
    __syncthreads();

    // ======== Phase C: ctx = P @ V^T (output 128x128, n = DK dense) ========
#pragma unroll
    for (int mt = 0; mt < 2; mt++)
#pragma unroll
        for (int nt = 0; nt < 4; nt++)
#pragma unroll
            for (int e = 0; e < 4; e++) acc[mt][nt][e] = 0.f;

    const int nchunkC = 7;                        // ceil(196/32)
    float4 pc[2];
    {
        int gk = c4 * 4;
#pragma unroll
        for (int it = 0; it < 2; ++it) {
            int rr = it * 64 + r_ld;
            pc[it] = *(const float4*)(sS + (size_t)rr * SSTRIDE + gk);
            b2[it] = *(const uint2*)(Vt + (size_t)rr * SEQ + gk);
        }
        a2[0] = cvt4h(pc[0]); a2[1] = cvt4h(pc[1]);
        stage_storeAB(sm, a2, b2, r_ld, c4);
    }
    __syncthreads();

    for (int c = 0; c < nchunkC; ++c) {
        if (c + 1 < nchunkC) {
            int gk = (c + 1) * KCHUNK + c4 * 4;
            bool kok = gk < SEQ;
#pragma unroll
            for (int it = 0; it < 2; ++it) {
                int rr = it * 64 + r_ld;
                pc[it] = *(const float4*)(sS + (size_t)rr * SSTRIDE + gk);   // pad zeroed
                b2[it] = kok ? *(const uint2*)(Vt + (size_t)rr * SEQ + gk) : uz;
            }
        }
        if (m_live)
            mma_chunk512s(smb + (uint32_t)(c & 1) * FBUF, acc, warp_m, warp_n, sub, i8);
        if (c + 1 < nchunkC) {
            a2[0] = cvt4h(pc[0]); a2[1] = cvt4h(pc[1]);
            stage_storeAB(sm + ((c + 1) & 1) * FBUF, a2, b2, r_ld, c4);
        }
        __syncthreads();
    }

    // epilogue -> ctx as fp16 hi/lo
#pragma unroll
    for (int mt = 0; mt < 2; ++mt) {
        int m = m0 + warp_m * 32 + mt * 16 + g;
#pragma unroll
        for (int nt = 0; nt < 4; ++nt) {
            int col = warp_n * 32 + nt * 8 + 2 * t4;
            float* d = acc[mt][nt];
            size_t base = ((size_t)b * SEQ) * DMODEL + h * DK + col;
            if (m < SEQ) {
                __half2 hh = __floats2half2_rn(d[0], d[1]);
                __half2 ll = __floats2half2_rn(d[0] - __low2float(hh), d[1] - __high2float(hh));
                size_t i0 = base + (size_t)m * DMODEL;
                *(uint32_t*)&g_ctxh[i0] = *(uint32_t*)&hh;
                *(uint32_t*)&g_ctxl[i0] = *(uint32_t*)&ll;
            }
            if (m + 8 < SEQ) {
                __half2 hh = __floats2half2_rn(d[2], d[3]);
                __half2 ll = __floats2half2_rn(d[2] - __low2float(hh), d[3] - __high2float(hh));
                size_t i1 = base + (size_t)(m + 8) * DMODEL;
                *(uint32_t*)&g_ctxh[i1] = *(uint32_t*)&hh;
                *(uint32_t*)&g_ctxl[i1] = *(uint32_t*)&ll;
            }
        }
    }
}

// ---------------- V transpose (fp16): g_vTh[bh][n][k] = g_vh[b][k][h*DK+n] ----------------
__global__ void vT_kernel()
{
    __shared__ __half t[32][40];
    int bh = blockIdx.z;
    int b = bh >> 3, h = bh & 7;
    int k0 = blockIdx.x * 32, n0 = blockIdx.y * 32;
    int tx = threadIdx.x, ty = threadIdx.y;   // 32 x 8
#pragma unroll
    for (int j = 0; j < 4; ++j) {
        int k = k0 + ty + j * 8;
        t[ty + j * 8][tx] = (k < SEQ)
            ? g_vh[((size_t)b * SEQ + k) * DMODEL + h * DK + n0 + tx] : __half(0.f);
    }
    __syncthreads();
#pragma unroll
    for (int j = 0; j < 4; ++j) {
        int n = n0 + ty + j * 8;
        int k = k0 + tx;
        if (k < SEQ)
            g_vTh[(size_t)bh * DK * SEQ + (size_t)n * SEQ + k] = t[tx][ty + j * 8];
    }
}

// ---------------- geometry embedding -> logw[b,h,n,m] ----------------
__global__ void logw_kernel(const float* __restrict__ boxes,
                            const float* __restrict__ WGw,
                            const float* __restrict__ WGb)
{
    __shared__ float sW[8][64];
    __shared__ float sB[8];
    __shared__ float sbn[4];
    int t = threadIdx.x;
    int b = blockIdx.x / SEQ;
    int n = blockIdx.x % SEQ;

    for (int i = t; i < 512; i += blockDim.x) sW[i >> 6][i & 63] = WGw[i];
    if (t < 8) sB[t] = WGb[t];
    if (t == 0) {
        const float* bp = boxes + ((size_t)b * SEQ + n) * 4;
        float xmn = bp[0], ymn = bp[1], xmx = bp[2], ymx = bp[3];
        sbn[0] = (xmn + xmx) * 0.5f;
        sbn[1] = (ymn + ymx) * 0.5f;
        sbn[2] = (xmx - xmn) + 1.0f;
        sbn[3] = (ymx - ymn) + 1.0f;
    }
    __syncthreads();

    int m = t;
    if (m >= SEQ) return;

    const float* bm = boxes + ((size_t)b * SEQ + m) * 4;
    float xmn = bm[0], ymn = bm[1], xmx = bm[2], ymx = bm[3];
    float cxm = (xmn + xmx) * 0.5f, cym = (ymn + ymx) * 0.5f;
    float wm = (xmx - xmn) + 1.0f, hm = (ymx - ymn) + 1.0f;
    float cxn = sbn[0], cyn = sbn[1], wn = sbn[2], hn = sbn[3];

    float pos[4];
    pos[0] = logf(fmaxf(fabsf((cxn - cxm) / wn), 1e-3f));
    pos[1] = logf(fmaxf(fabsf((cyn - cym) / hn), 1e-3f));
    pos[2] = logf(wn / wm);
    pos[3] = logf(hn / hm);

    float acc[8];
#pragma unroll
    for (int h = 0; h < 8; h++) acc[h] = sB[h];

#pragma unroll
    for (int c = 0; c < 4; c++) {
        float p = 100.0f * pos[c];
#pragma unroll
        for (int j = 0; j < 8; j++) {
            float s, co;
            __sincosf(p * c_dim[j], &s, &co);
            int f = c * 8 + j;
#pragma unroll
            for (int h = 0; h < 8; h++)
                acc[h] += s * sW[h][f] + co * sW[h][f + 32];
        }
    }

    size_t base = ((size_t)b * HEADS) * SEQ * SEQ + (size_t)n * SEQ + m;
#pragma unroll
    for (int h = 0; h < 8; h++) {
        float wg = fmaxf(acc[h], 1e-6f);
        g_logw[base + (size_t)h * SEQ * SEQ] = logf(wg);
    }
}

// ---------------- launch ----------------
extern "C" void kernel_launch(void* const* d_in, const int* in_sizes, int n_in,
                              void* d_out, int out_size)
{
    const float* xq  = (const float*)d_in[0];
    const float* xk  = (const float*)d_in[1];
    const float* xv  = (const float*)d_in[2];
    const float* box = (const float*)d_in[3];
    const float* Wq  = (const float*)d_in[4];
    const float* bq  = (const float*)d_in[5];
    const float* Wk  = (const float*)d_in[6];
    const float* bk  = (const float*)d_in[7];
    const float* Wv  = (const float*)d_in[8];
    const float* bv  = (const float*)d_in[9];
    const float* Wo  = (const float*)d_in[10];
    const float* bo  = (const float*)d_in[11];
    const float* WGw = (const float*)d_in[12];
    const float* WGb = (const float*)d_in[13];
    float* out = (float*)d_out;

    cudaFuncSetAttribute(qkv_mma,    cudaFuncAttributeMaxDynamicSharedMemorySize, PSMEM);
    cudaFuncSetAttribute(out_mma,    cudaFuncAttributeMaxDynamicSharedMemorySize, PSMEM);
    cudaFuncSetAttribute(fused_attn, cudaFuncAttributeMaxDynamicSharedMemorySize, SMEM_FUSED);

    // 1) Q/K/V projections (fp16x2 A-accuracy, fp16 outputs)
    qkv_mma<<<dim3(DMODEL / 128, MROWS / 128, 3), 256, PSMEM>>>(
        xq, xk, xv, Wq, Wk, Wv, bq, bk, bv);

    // 2) transpose V per head (fp16)
    vT_kernel<<<dim3(7, 4, BATCH * HEADS), dim3(32, 8)>>>();

    // 3) geometry relation log-weights
    logw_kernel<<<BATCH * SEQ, 224>>>(box, WGw, WGb);

    // 4) fused: S = QK^T/sqrt(dk)+logw -> softmax -> P@V  (single-fp16 MMAs)
    fused_attn<<<dim3(2, BATCH * HEADS), 512, SMEM_FUSED>>>();

    // 5) output projection into d_out (pre-split fp16 ctx)
    out_mma<<<dim3(DMODEL / 128, MROWS / 128, 1), 256, PSMEM>>>(Wo, bo, out);
}

// round 17
// speedup vs baseline: 1.5353x; 1.1333x over previous
#include <cuda_runtime.h>
#include <cuda_bf16.h>
#include <cuda_fp16.h>
#include <math.h>
#include <stdint.h>

#define BATCH 32
#define SEQ 196
#define DMODEL 1024
#define HEADS 8
#define DK 128
#define MROWS (BATCH*SEQ)            // 6272

// ---------------- scratch (static device arrays; no allocations) ----------------
__device__ __half g_qh[MROWS*DMODEL];                   // Q (fp16)
__device__ __half g_kh[MROWS*DMODEL];                   // K (fp16)
__device__ __half g_vh[MROWS*DMODEL];                   // V (fp16)
__device__ __half g_vTh[(size_t)BATCH*HEADS*DK*SEQ];    // V^T per head (fp16)
__device__ __half g_ctxh[MROWS*DMODEL];                 // ctx (fp16)
__device__ float  g_logw[(size_t)BATCH*HEADS*SEQ*SEQ];  // geometry log-weights

__constant__ float c_dim[8] = {
    1.0f, 0.4216965034285822f, 0.1778279410038923f, 0.07498942093324558f,
    0.03162277660168379f, 0.013335214321633241f, 0.005623413251903491f,
    0.0023713737056616554f
};

// ============================================================================
// common helpers
// ============================================================================
__device__ __forceinline__ uint32_t smem_u32(const void* p) {
    uint32_t a;
    asm("{ .reg .u64 t; cvta.to.shared.u64 t, %1; cvt.u32.u64 %0, t; }" : "=r"(a) : "l"(p));
    return a;
}

__device__ __forceinline__ void ldsm4(uint32_t r[4], uint32_t addr) {
    asm volatile("ldmatrix.sync.aligned.m8n8.x4.shared.b16 {%0,%1,%2,%3}, [%4];"
        : "=r"(r[0]), "=r"(r[1]), "=r"(r[2]), "=r"(r[3]) : "r"(addr));
}

__device__ __forceinline__ void mma16816h(float d[4], const uint32_t a[4], const uint32_t b[2]) {
    asm volatile("mma.sync.aligned.m16n8k16.row.col.f32.f16.f16.f32 "
        "{%0,%1,%2,%3}, {%4,%5,%6,%7}, {%8,%9}, {%0,%1,%2,%3};"
        : "+f"(d[0]), "+f"(d[1]), "+f"(d[2]), "+f"(d[3])
        : "r"(a[0]), "r"(a[1]), "r"(a[2]), "r"(a[3]), "r"(b[0]), "r"(b[1]));
}

__device__ __forceinline__ uint2 cvt4h(float4 v) {
    __half2 h0 = __floats2half2_rn(v.x, v.y);
    __half2 h1 = __floats2half2_rn(v.z, v.w);
    return make_uint2(*(uint32_t*)&h0, *(uint32_t*)&h1);
}

// ============================================================================
// projection GEMM (single fp16 x fp16): 256 threads, 8 warps, warp tile 32x64.
// ============================================================================
#define PKC 32
#define PNCH (DMODEL / PKC)          // 32
#define PGS 80                       // 32 fp16 = 64B + 16B pad
#define PA_OFF 0
#define PB_OFF (128*PGS)             // 10240
#define PBUF  (2*128*PGS)            // 20480
#define PSMEM (2*PBUF)               // 40960

// one 32-K chunk: 2 k16 steps, per step 6 LDSM + 16 fp16 MMAs
__device__ __forceinline__ void mma_chunk_p(uint32_t base, float acc[2][8][4],
                                            int warp_m, int warp_n, int sub, int i8)
{
#pragma unroll
    for (int ks = 0; ks < 2; ++ks) {
        const int kofs = ks * 16;
        uint32_t aH[2][4];
#pragma unroll
        for (int mt = 0; mt < 2; ++mt) {
            int row = warp_m * 32 + mt * 16 + (sub & 1) * 8 + i8;
            int col = kofs + (sub >> 1) * 8;
            ldsm4(aH[mt], base + PA_OFF + (uint32_t)row * PGS + col * 2);
        }
#pragma unroll
        for (int ntp = 0; ntp < 4; ++ntp) {
            int nr = warp_n * 64 + ntp * 16 + (sub >> 1) * 8 + i8;
            int nc = kofs + (sub & 1) * 8;
            uint32_t bH[4];
            ldsm4(bH, base + PB_OFF + (uint32_t)nr * PGS + nc * 2);
#pragma unroll
            for (int mt = 0; mt < 2; ++mt) {
#pragma unroll
                for (int nh = 0; nh < 2; ++nh)
                    mma16816h(acc[mt][ntp * 2 + nh], aH[mt], &bH[nh * 2]);
            }
        }
    }
}

// PRE_A = 0: X fp32, converted at staging. PRE_A = 1: Ah pre-converted fp16.
// EPI 0: fp32 Y (+bias). EPI 2: single fp16 -> Yh.
template<int PRE_A, int EPI>
__device__ __forceinline__ void fp16_gemm(const float* __restrict__ X,
                                          const __half* __restrict__ Ah,
                                          const float* __restrict__ W,
                                          const float* __restrict__ bias,
                                          float* __restrict__ Y,
                                          __half* __restrict__ Yh)
{
    extern __shared__ __align__(16) char sm[];
    const uint32_t smb = smem_u32(sm);
    const int tid = threadIdx.x;
    const int lane = tid & 31, w = tid >> 5;
    const int warp_m = w & 3, warp_n = w >> 2;
    const int m0 = blockIdx.y * 128, n0 = blockIdx.x * 128;
    const int r_ld = tid >> 3, c4 = tid & 7;
    const int sub = lane >> 3, i8 = lane & 7;

    float acc[2][8][4];
#pragma unroll
    for (int mt = 0; mt < 2; mt++)
#pragma unroll
        for (int nt = 0; nt < 8; nt++)
#pragma unroll
            for (int e = 0; e < 4; e++) acc[mt][nt][e] = 0.f;

    float4 pa[4], pb[4];
    uint2 ah[4];

    auto ldg = [&](int kc) {
        int gk = kc + c4 * 4;
#pragma unroll
        for (int it = 0; it < 4; ++it) {
            size_t rowA = (size_t)(m0 + it * 32 + r_ld) * DMODEL + gk;
            if (PRE_A) ah[it] = *(const uint2*)(Ah + rowA);
            else       pa[it] = *(const float4*)(X + rowA);
            pb[it] = *(const float4*)(W + (size_t)(n0 + it * 32 + r_ld) * DMODEL + gk);
        }
    };
    auto sts = [&](char* bp) {
#pragma unroll
        for (int it = 0; it < 4; ++it) {
            uint32_t off = (uint32_t)(it * 32 + r_ld) * PGS + c4 * 8;
            *(uint2*)(bp + PA_OFF + off) = PRE_A ? ah[it] : cvt4h(pa[it]);
            *(uint2*)(bp + PB_OFF + off) = cvt4h(pb[it]);
        }
    };

    ldg(0);
    sts(sm);
    __syncthreads();

    for (int c = 0; c < PNCH; ++c) {
        if (c + 1 < PNCH) ldg((c + 1) * PKC);
        mma_chunk_p(smb + (uint32_t)(c & 1) * PBUF, acc, warp_m, warp_n, sub, i8);
        if (c + 1 < PNCH) sts(sm + ((c + 1) & 1) * PBUF);
        __syncthreads();
    }

    const int g = lane >> 2, t4 = lane & 3;
#pragma unroll
    for (int mt = 0; mt < 2; ++mt) {
        int row = m0 + warp_m * 32 + mt * 16 + g;
#pragma unroll
        for (int nt = 0; nt < 8; ++nt) {
            int col = n0 + warp_n * 64 + nt * 8 + 2 * t4;
            float b0 = bias[col], b1 = bias[col + 1];
            float* d = acc[mt][nt];
            float v0 = d[0] + b0, v1 = d[1] + b1;
            float v2 = d[2] + b0, v3 = d[3] + b1;
            size_t i0 = (size_t)row * DMODEL + col;
            size_t i1 = (size_t)(row + 8) * DMODEL + col;
            if (EPI == 0) {
                *(float2*)&Y[i0] = make_float2(v0, v1);
                *(float2*)&Y[i1] = make_float2(v2, v3);
            } else {
                __half2 h0 = __floats2half2_rn(v0, v1);
                __half2 h1 = __floats2half2_rn(v2, v3);
                *(uint32_t*)&Yh[i0] = *(uint32_t*)&h0;
                *(uint32_t*)&Yh[i1] = *(uint32_t*)&h1;
            }
        }
    }
}

__global__ void __launch_bounds__(256, 1)
qkv_mma(const float* __restrict__ xq, const float* __restrict__ xk,
        const float* __restrict__ xv,
        const float* __restrict__ wq, const float* __restrict__ wk,
        const float* __restrict__ wv,
        const float* __restrict__ bq, const float* __restrict__ bk,
        const float* __restrict__ bv)
{
    int z = blockIdx.z;
    if (z == 0)      fp16_gemm<0,2>(xq, nullptr, wq, bq, nullptr, g_qh);
    else if (z == 1) fp16_gemm<0,2>(xk, nullptr, wk, bk, nullptr, g_kh);
    else             fp16_gemm<0,2>(xv, nullptr, wv, bv, nullptr, g_vh);
}

__global__ void __launch_bounds__(256, 1)
out_mma(const float* __restrict__ Wo, const float* __restrict__ bo,
        float* __restrict__ Y)
{
    fp16_gemm<1,0>(nullptr, g_ctxh, Wo, bo, Y, nullptr);
}

// ============================================================================
// fused attention, 512 threads / 16 warps, warp tile 32x32, dead-tile skip.
// Single-fp16 A (Q / P) x single-fp16 B (K / V).  ctx emitted single fp16.
// ============================================================================
#define KCHUNK 32
#define FGS 80                       // 32 fp16 = 64B + 16B pad
#define F_AHI 0
#define F_BHI (128*FGS)              // 10240
#define FBUF  (2*128*FGS)            // 20480
#define SSTRIDE 224
#define SMEM_FUSED (2*FBUF + 128*SSTRIDE*4)   // 40960 + 114688 = 155648

__device__ __forceinline__ void stage_storeAB(char* bp, const uint2 a2[2],
                                              const uint2 b2[2], int r_ld, int c4)
{
#pragma unroll
    for (int it = 0; it < 2; ++it) {
        uint32_t off = (uint32_t)(it * 64 + r_ld) * FGS + c4 * 8;
        *(uint2*)(bp + F_AHI + off) = a2[it];
        *(uint2*)(bp + F_BHI + off) = b2[it];
    }
}

__device__ __forceinline__ void mma_chunk512s(uint32_t base, float acc[2][4][4],
                                              int warp_m, int warp_n, int sub, int i8)
{
#pragma unroll
    for (int ks = 0; ks < 2; ++ks) {
        const int kofs = ks * 16;
        uint32_t aH[2][4];
#pragma unroll
        for (int mt = 0; mt < 2; ++mt) {
            int row = warp_m * 32 + mt * 16 + (sub & 1) * 8 + i8;
            int col = kofs + (sub >> 1) * 8;
            ldsm4(aH[mt], base + F_AHI + (uint32_t)row * FGS + col * 2);
        }
#pragma unroll
        for (int ntp = 0; ntp < 2; ++ntp) {
            int nr = warp_n * 32 + ntp * 16 + (sub >> 1) * 8 + i8;
            int nc = kofs + (sub & 1) * 8;
            uint32_t bH[4];
            ldsm4(bH, base + F_BHI + (uint32_t)nr * FGS + nc * 2);
#pragma unroll
            for (int mt = 0; mt < 2; ++mt) {
#pragma unroll
                for (int nh = 0; nh < 2; ++nh)
                    mma16816h(acc[mt][ntp * 2 + nh], aH[mt], &bH[nh * 2]);
            }
        }
    }
}

__global__ void __launch_bounds__(512, 1)
fused_attn()
{
    extern __shared__ __align__(16) char sm[];
    const uint32_t smb = smem_u32(sm);
    float* sS = (float*)(sm + 2 * FBUF);         // 128 x SSTRIDE fp32

    const int bh = blockIdx.y;
    const int b = bh >> 3, h = bh & 7;
    const int m0 = blockIdx.x * 128;
    const __half* Qh = g_qh + (size_t)b * SEQ * DMODEL + h * DK;
    const __half* Kh = g_kh + (size_t)b * SEQ * DMODEL + h * DK;
    const float*  LW = g_logw + (size_t)bh * SEQ * SEQ;
    const __half* Vt = g_vTh + (size_t)bh * DK * SEQ;

    const int tid = threadIdx.x;
    const int lane = tid & 31, w = tid >> 5;     // w: 0..15
    const int warp_m = w & 3, warp_n = w >> 2;   // 4 x 4 warp grid
    const int r_ld = tid >> 3, c4 = tid & 7;     // r_ld: 0..63
    const int sub = lane >> 3, i8 = lane & 7;
    const int g = lane >> 2, t4 = lane & 3;
    const uint2 uz = make_uint2(0u, 0u);

    const bool m_live = (m0 + warp_m * 32) < SEQ;

    float acc[2][4][4];
    uint2 a2[2], b2[2];

    // ======== Phase A: S = Q K^T * scale + logw (two 128x128 n-halves) ========
    const float scale = 0.08838834764831845f;   // 1/sqrt(128)
#pragma unroll 1
    for (int nt2 = 0; nt2 < 2; ++nt2) {
        const int n0 = nt2 * 128;
        const bool live = m_live && ((n0 + warp_n * 32) < SEQ);
#pragma unroll
        for (int mt = 0; mt < 2; mt++)
#pragma unroll
            for (int nt = 0; nt < 4; nt++)
#pragma unroll
                for (int e = 0; e < 4; e++) acc[mt][nt][e] = 0.f;

        {
            int gk = c4 * 4;
#pragma unroll
            for (int it = 0; it < 2; ++it) {
                int am = m0 + it * 64 + r_ld;
                int bn = n0 + it * 64 + r_ld;
                a2[it] = (am < SEQ) ? *(const uint2*)(Qh + (size_t)am * DMODEL + gk) : uz;
                b2[it] = (bn < SEQ) ? *(const uint2*)(Kh + (size_t)bn * DMODEL + gk) : uz;
            }
            stage_storeAB(sm, a2, b2, r_ld, c4);
        }
        __syncthreads();

        for (int c = 0; c < 4; ++c) {          // DK=128 -> 4 chunks
            if (c + 1 < 4) {
                int gk = (c + 1) * KCHUNK + c4 * 4;
#pragma unroll
                for (int it = 0; it < 2; ++it) {
                    int am = m0 + it * 64 + r_ld;
                    int bn = n0 + it * 64 + r_ld;
                    a2[it] = (am < SEQ) ? *(const uint2*)(Qh + (size_t)am * DMODEL + gk) : uz;
                    b2[it] = (bn < SEQ) ? *(const uint2*)(Kh + (size_t)bn * DMODEL + gk) : uz;
                }
            }
            if (live)
                mma_chunk512s(smb + (uint32_t)(c & 1) * FBUF, acc, warp_m, warp_n, sub, i8);
            if (c + 1 < 4)
                stage_storeAB(sm + ((c + 1) & 1) * FBUF, a2, b2, r_ld, c4);
            __syncthreads();
        }

        // epilogue -> sS (+logw)
#pragma unroll
        for (int mt = 0; mt < 2; ++mt) {
            int rl = warp_m * 32 + mt * 16 + g;        // local row 0..127
            int m = m0 + rl;
#pragma unroll
            for (int nt = 0; nt < 4; ++nt) {
                int col = n0 + warp_n * 32 + nt * 8 + 2 * t4;
                float* d = acc[mt][nt];
                if (col < SEQ) {
                    bool mok = (m < SEQ);
                    float l0 = mok ? LW[(size_t)m * SEQ + col] : 0.f;
                    float l1 = mok ? LW[(size_t)m * SEQ + col + 1] : 0.f;
                    *(float2*)&sS[(size_t)rl * SSTRIDE + col] =
                        make_float2(fmaf(d[0], scale, l0), fmaf(d[1], scale, l1));
                    bool m8 = (m + 8 < SEQ);
                    float l2 = m8 ? LW[(size_t)(m + 8) * SEQ + col] : 0.f;
                    float l3 = m8 ? LW[(size_t)(m + 8) * SEQ + col + 1] : 0.f;
                    *(float2*)&sS[(size_t)(rl + 8) * SSTRIDE + col] =
                        make_float2(fmaf(d[2], scale, l2), fmaf(d[3], scale, l3));
                }
            }
        }
        __syncthreads();
    }

    // ======== Phase B: softmax rows in SMEM (16 warps x 8 rows) ========
    {
#pragma unroll 1
        for (int j = 0; j < 8; ++j) {
            int r = w * 8 + j;
            float* row = sS + (size_t)r * SSTRIDE;
            float x[7];
            float mx = -1e30f;
#pragma unroll
            for (int i = 0; i < 7; ++i) {
                int cidx = lane + i * 32;
                x[i] = (cidx < SEQ) ? row[cidx] : -1e30f;
                mx = fmaxf(mx, x[i]);
            }
#pragma unroll
            for (int o = 16; o > 0; o >>= 1) mx = fmaxf(mx, __shfl_xor_sync(0xffffffffu, mx, o));
            float sum = 0.f;
#pragma unroll
            for (int i = 0; i < 7; ++i) {
                x[i] = expf(x[i] - mx);
                sum += x[i];
            }
#pragma unroll
            for (int o = 16; o > 0; o >>= 1) sum += __shfl_xor_sync(0xffffffffu, sum, o);
            float inv = 1.0f / sum;
#pragma unroll
            for (int i = 0; i < 7; ++i) {
                int cidx = lane + i * 32;
                if (cidx < SEQ) row[cidx] = x[i] * inv;
            }
            if (lane < 28) row[SEQ + lane] = 0.f;     // zero pad cols 196..223
        }
    }
    __syncthreads();

    // ======== Phase C: ctx = P @ V^T (output 128x128, n = DK dense) ========
#pragma unroll
    for (int mt = 0; mt < 2; mt++)
#pragma unroll
        for (int nt = 0; nt < 4; nt++)
#pragma unroll
            for (int e = 0; e < 4; e++) acc[mt][nt][e] = 0.f;

    const int nchunkC = 7;                        // ceil(196/32)
    float4 pc[2];
    {
        int gk = c4 * 4;
#pragma unroll
        for (int it = 0; it < 2; ++it) {
            int rr = it * 64 + r_ld;
            pc[it] = *(const float4*)(sS + (size_t)rr * SSTRIDE + gk);
            b2[it] = *(const uint2*)(Vt + (size_t)rr * SEQ + gk);
        }
        a2[0] = cvt4h(pc[0]); a2[1] = cvt4h(pc[1]);
        stage_storeAB(sm, a2, b2, r_ld, c4);
    }
    __syncthreads();

    for (int c = 0; c < nchunkC; ++c) {
        if (c + 1 < nchunkC) {
            int gk = (c + 1) * KCHUNK + c4 * 4;
            bool kok = gk < SEQ;
#pragma unroll
            for (int it = 0; it < 2; ++it) {
                int rr = it * 64 + r_ld;
                pc[it] = *(const float4*)(sS + (size_t)rr * SSTRIDE + gk);   // pad zeroed
                b2[it] = kok ? *(const uint2*)(Vt + (size_t)rr * SEQ + gk) : uz;
            }
        }
        if (m_live)
            mma_chunk512s(smb + (uint32_t)(c & 1) * FBUF, acc, warp_m, warp_n, sub, i8);
        if (c + 1 < nchunkC) {
            a2[0] = cvt4h(pc[0]); a2[1] = cvt4h(pc[1]);
            stage_storeAB(sm + ((c + 1) & 1) * FBUF, a2, b2, r_ld, c4);
        }
        __syncthreads();
    }

    // epilogue -> ctx as single fp16
#pragma unroll
    for (int mt = 0; mt < 2; ++mt) {
        int m = m0 + warp_m * 32 + mt * 16 + g;
#pragma unroll
        for (int nt = 0; nt < 4; ++nt) {
            int col = warp_n * 32 + nt * 8 + 2 * t4;
            float* d = acc[mt][nt];
            size_t base = ((size_t)b * SEQ) * DMODEL + h * DK + col;
            if (m < SEQ) {
                __half2 hh = __floats2half2_rn(d[0], d[1]);
                *(uint32_t*)&g_ctxh[base + (size_t)m * DMODEL] = *(uint32_t*)&hh;
            }
            if (m + 8 < SEQ) {
                __half2 hh = __floats2half2_rn(d[2], d[3]);
                *(uint32_t*)&g_ctxh[base + (size_t)(m + 8) * DMODEL] = *(uint32_t*)&hh;
            }
        }
    }
}

// ---------------- V transpose (fp16): g_vTh[bh][n][k] = g_vh[b][k][h*DK+n] ----------------
__global__ void vT_kernel()
{
    __shared__ __half t[32][40];
    int bh = blockIdx.z;
    int b = bh >> 3, h = bh & 7;
    int k0 = blockIdx.x * 32, n0 = blockIdx.y * 32;
    int tx = threadIdx.x, ty = threadIdx.y;   // 32 x 8
#pragma unroll
    for (int j = 0; j < 4; ++j) {
        int k = k0 + ty + j * 8;
        t[ty + j * 8][tx] = (k < SEQ)
            ? g_vh[((size_t)b * SEQ + k) * DMODEL + h * DK + n0 + tx] : __half(0.f);
    }
    __syncthreads();
#pragma unroll
    for (int j = 0; j < 4; ++j) {
        int n = n0 + ty + j * 8;
        int k = k0 + tx;
        if (k < SEQ)
            g_vTh[(size_t)bh * DK * SEQ + (size_t)n * SEQ + k] = t[tx][ty + j * 8];
    }
}

// ---------------- geometry embedding -> logw[b,h,n,m] ----------------
__global__ void logw_kernel(const float* __restrict__ boxes,
                            const float* __restrict__ WGw,
                            const float* __restrict__ WGb)
{
    __shared__ float sW[8][64];
    __shared__ float sB[8];
    __shared__ float sbn[4];
    int t = threadIdx.x;
    int b = blockIdx.x / SEQ;
    int n = blockIdx.x % SEQ;

    for (int i = t; i < 512; i += blockDim.x) sW[i >> 6][i & 63] = WGw[i];
    if (t < 8) sB[t] = WGb[t];
    if (t == 0) {
        const float* bp = boxes + ((size_t)b * SEQ + n) * 4;
        float xmn = bp[0], ymn = bp[1], xmx = bp[2], ymx = bp[3];
        sbn[0] = (xmn + xmx) * 0.5f;
        sbn[1] = (ymn + ymx) * 0.5f;
        sbn[2] = (xmx - xmn) + 1.0f;
        sbn[3] = (ymx - ymn) + 1.0f;
    }
    __syncthreads();

    int m = t;
    if (m >= SEQ) return;

    const float* bm = boxes + ((size_t)b * SEQ + m) * 4;
    float xmn = bm[0], ymn = bm[1], xmx = bm[2], ymx = bm[3];
    float cxm = (xmn + xmx) * 0.5f, cym = (ymn + ymx) * 0.5f;
    float wm = (xmx - xmn) + 1.0f, hm = (ymx - ymn) + 1.0f;
    float cxn = sbn[0], cyn = sbn[1], wn = sbn[2], hn = sbn[3];

    float pos[4];
    pos[0] = logf(fmaxf(fabsf((cxn - cxm) / wn), 1e-3f));
    pos[1] = logf(fmaxf(fabsf((cyn - cym) / hn), 1e-3f));
    pos[2] = logf(wn / wm);
    pos[3] = logf(hn / hm);

    float acc[8];
#pragma unroll
    for (int h = 0; h < 8; h++) acc[h] = sB[h];

#pragma unroll
    for (int c = 0; c < 4; c++) {
        float p = 100.0f * pos[c];
#pragma unroll
        for (int j = 0; j < 8; j++) {
            float s, co;
            __sincosf(p * c_dim[j], &s, &co);
            int f = c * 8 + j;
#pragma unroll
            for (int h = 0; h < 8; h++)
                acc[h] += s * sW[h][f] + co * sW[h][f + 32];
        }
    }

    size_t base = ((size_t)b * HEADS) * SEQ * SEQ + (size_t)n * SEQ + m;
#pragma unroll
    for (int h = 0; h < 8; h++) {
        float wg = fmaxf(acc[h], 1e-6f);
        g_logw[base + (size_t)h * SEQ * SEQ] = logf(wg);
    }
}

// ---------------- launch ----------------
extern "C" void kernel_launch(void* const* d_in, const int* in_sizes, int n_in,
                              void* d_out, int out_size)
{
    const float* xq  = (const float*)d_in[0];
    const float* xk  = (const float*)d_in[1];
    const float* xv  = (const float*)d_in[2];
    const float* box = (const float*)d_in[3];
    const float* Wq  = (const float*)d_in[4];
    const float* bq  = (const float*)d_in[5];
    const float* Wk  = (const float*)d_in[6];
    const float* bk  = (const float*)d_in[7];
    const float* Wv  = (const float*)d_in[8];
    const float* bv  = (const float*)d_in[9];
    const float* Wo  = (const float*)d_in[10];
    const float* bo  = (const float*)d_in[11];
    const float* WGw = (const float*)d_in[12];
    const float* WGb = (const float*)d_in[13];
    float* out = (float*)d_out;

    cudaFuncSetAttribute(qkv_mma,    cudaFuncAttributeMaxDynamicSharedMemorySize, PSMEM);
    cudaFuncSetAttribute(out_mma,    cudaFuncAttributeMaxDynamicSharedMemorySize, PSMEM);
    cudaFuncSetAttribute(fused_attn, cudaFuncAttributeMaxDynamicSharedMemorySize, SMEM_FUSED);

    // 1) Q/K/V projections (single-fp16 MMA)
    qkv_mma<<<dim3(DMODEL / 128, MROWS / 128, 3), 256, PSMEM>>>(
        xq, xk, xv, Wq, Wk, Wv, bq, bk, bv);

    // 2) transpose V per head (fp16)
    vT_kernel<<<dim3(7, 4, BATCH * HEADS), dim3(32, 8)>>>();

    // 3) geometry relation log-weights
    logw_kernel<<<BATCH * SEQ, 224>>>(box, WGw, WGb);

    // 4) fused: S = QK^T/sqrt(dk)+logw -> softmax -> P@V  (single-fp16 MMAs)
    fused_attn<<<dim3(2, BATCH * HEADS), 512, SMEM_FUSED>>>();

    // 5) output projection into d_out (single-fp16 ctx)
    out_mma<<<dim3(DMODEL / 128, MROWS / 128, 1), 256, PSMEM>>>(Wo, bo, out);
}